// round 2
// baseline (speedup 1.0000x reference)
#include <cuda_runtime.h>
#include <math.h>

#define N_ENT   50000
#define NREL    200
#define DIM     128
#define NB      4
#define E_EDGES 200000
#define S_SAMP  20000
#define WN      640   /* (NB+1)*DIM : [basis0..basis3 | root] */

// ---------------- scratch (device globals; no runtime allocation) ----------
__device__ float g_Wcat[DIM * WN];                    //  320 KB
__device__ float g_Y[(size_t)N_ENT * WN];             //  128 MB
__device__ float g_AGG[(size_t)N_ENT * DIM];          // 25.6 MB
__device__ float g_CNT[N_ENT];                        //  200 KB
__device__ float g_XB[(size_t)N_ENT * DIM];           // 25.6 MB
__device__ float g_XC[(size_t)N_ENT * DIM];           // 25.6 MB
__device__ float g_relT[NREL * DIM];
__device__ float g_relC[NREL * DIM];

// ---------------- helpers ---------------------------------------------------
__global__ void zerok(float* p, long long n) {
    long long i = (long long)blockIdx.x * blockDim.x + threadIdx.x;
    long long stride = (long long)gridDim.x * blockDim.x;
    for (; i < n; i += stride) p[i] = 0.0f;
}

__global__ void count_k(const int* __restrict__ dst) {
    int i = blockIdx.x * blockDim.x + threadIdx.x;
    if (i < E_EDGES) atomicAdd(&g_CNT[dst[i]], 1.0f);
}

// replace counts with reciprocals so finalize can multiply
__global__ void invcnt_k() {
    int i = blockIdx.x * blockDim.x + threadIdx.x;
    if (i < N_ENT) {
        float c = g_CNT[i];
        c = c > 1.0f ? c : 1.0f;
        g_CNT[i] = 1.0f / c;
    }
}

// Wcat[k, c] : c<512 -> basis[b=c/128][k][c%128] ; c>=512 -> root[k][c-512]
__global__ void build_wcat(const float* __restrict__ basis,
                           const float* __restrict__ root) {
    int idx = blockIdx.x * blockDim.x + threadIdx.x;  // DIM*WN
    if (idx >= DIM * WN) return;
    int k = idx / WN, c = idx % WN;
    float v;
    if (c < NB * DIM) {
        int b = c >> 7, j = c & 127;
        v = basis[((size_t)b * DIM + k) * DIM + j];
    } else {
        v = root[(size_t)k * DIM + (c - NB * DIM)];
    }
    g_Wcat[idx] = v;
}

// ---------------- packed-fp32 GEMM: C[M,N] = A[idx[M],K] @ B[K,N] ----------
// BM=64, BN=128, BK=16, 256 threads, 4x8 microtile via fma.rn.f32x2.
__device__ __forceinline__ void ffma2(unsigned long long& d,
                                      unsigned long long a,
                                      unsigned long long b) {
    asm("fma.rn.f32x2 %0, %1, %2, %0;" : "+l"(d) : "l"(a), "l"(b));
}
__device__ __forceinline__ unsigned long long dup2(float x) {
    unsigned long long r;
    asm("mov.b64 %0, {%1, %1};" : "=l"(r) : "f"(x));
    return r;
}

__global__ void gemm128(const float* __restrict__ A, const int* __restrict__ aidx,
                        const float* __restrict__ B, float* __restrict__ C,
                        int M, int N, int K) {
    __shared__ float As[16][64];
    __shared__ float Bs[16][128];
    int tid = threadIdx.x;
    int tx = tid & 15;          // N dir : 8 cols each
    int ty = tid >> 4;          // M dir : 4 rows each
    int m0 = blockIdx.x * 64;
    int n0 = blockIdx.y * 128;

    // A tile loader: 64 rows x 4 float4; row indirection hoisted out of k-loop
    int arow = tid >> 2, ak4 = tid & 3;
    int ga = m0 + arow;
    bool avalid = ga < M;
    int garow = avalid ? (aidx ? aidx[ga] : ga) : 0;

    // B tile loader: 16 rows x 32 float4 -> 2 float4/thread
    int brow = tid >> 4;
    int bc = (tid & 15) * 8;

    unsigned long long acc[4][4];
#pragma unroll
    for (int i = 0; i < 4; i++)
#pragma unroll
        for (int j = 0; j < 4; j++) acc[i][j] = 0ull;

    for (int k0 = 0; k0 < K; k0 += 16) {
        float4 av = make_float4(0.f, 0.f, 0.f, 0.f);
        if (avalid)
            av = *(const float4*)(A + (size_t)garow * K + k0 + ak4 * 4);
        As[ak4 * 4 + 0][arow] = av.x;
        As[ak4 * 4 + 1][arow] = av.y;
        As[ak4 * 4 + 2][arow] = av.z;
        As[ak4 * 4 + 3][arow] = av.w;

        const float4* bsrc = (const float4*)(B + (size_t)(k0 + brow) * N + n0 + bc);
        *(float4*)(&Bs[brow][bc]) = bsrc[0];
        *(float4*)(&Bs[brow][bc + 4]) = bsrc[1];
        __syncthreads();

#pragma unroll
        for (int k = 0; k < 16; k++) {
            float4 a = *(const float4*)(&As[k][ty * 4]);
            ulonglong2 b01 = *(const ulonglong2*)(&Bs[k][tx * 8]);
            ulonglong2 b23 = *(const ulonglong2*)(&Bs[k][tx * 8 + 4]);
            unsigned long long da;
            da = dup2(a.x);
            ffma2(acc[0][0], da, b01.x); ffma2(acc[0][1], da, b01.y);
            ffma2(acc[0][2], da, b23.x); ffma2(acc[0][3], da, b23.y);
            da = dup2(a.y);
            ffma2(acc[1][0], da, b01.x); ffma2(acc[1][1], da, b01.y);
            ffma2(acc[1][2], da, b23.x); ffma2(acc[1][3], da, b23.y);
            da = dup2(a.z);
            ffma2(acc[2][0], da, b01.x); ffma2(acc[2][1], da, b01.y);
            ffma2(acc[2][2], da, b23.x); ffma2(acc[2][3], da, b23.y);
            da = dup2(a.w);
            ffma2(acc[3][0], da, b01.x); ffma2(acc[3][1], da, b01.y);
            ffma2(acc[3][2], da, b23.x); ffma2(acc[3][3], da, b23.y);
        }
        __syncthreads();
    }

#pragma unroll
    for (int i = 0; i < 4; i++) {
        int row = m0 + ty * 4 + i;
        if (row < M) {
            unsigned long long* op =
                (unsigned long long*)(C + (size_t)row * N + n0 + tx * 8);
            *(ulonglong2*)(op + 0) = make_ulonglong2(acc[i][0], acc[i][1]);
            *(ulonglong2*)(op + 2) = make_ulonglong2(acc[i][2], acc[i][3]);
        }
    }
}

// ---------------- edge message scatter --------------------------------------
// warp per edge: msg = norm * sum_b att[type][b] * Y[src, b*128 : b*128+128]
// vector red.global.add.v4.f32 into AGG[dst].
__global__ void edge_msg(const int* __restrict__ src, const int* __restrict__ dst,
                         const int* __restrict__ etype, const float* __restrict__ enorm,
                         const float* __restrict__ att) {
    int warp = (blockIdx.x * blockDim.x + threadIdx.x) >> 5;
    int lane = threadIdx.x & 31;
    if (warp >= E_EDGES) return;
    int s = src[warp];
    int d = dst[warp];
    int t = etype[warp];
    float nrm = enorm[warp];
    float4 a = *(const float4*)(att + (size_t)t * 4);
    a.x *= nrm; a.y *= nrm; a.z *= nrm; a.w *= nrm;

    const float4* y = (const float4*)(g_Y + (size_t)s * WN);
    float4 y0 = y[lane];
    float4 y1 = y[32 + lane];
    float4 y2 = y[64 + lane];
    float4 y3 = y[96 + lane];

    float4 m;
    m.x = a.x * y0.x + a.y * y1.x + a.z * y2.x + a.w * y3.x;
    m.y = a.x * y0.y + a.y * y1.y + a.z * y2.y + a.w * y3.y;
    m.z = a.x * y0.z + a.y * y1.z + a.z * y2.z + a.w * y3.z;
    m.w = a.x * y0.w + a.y * y1.w + a.z * y2.w + a.w * y3.w;

    float* o = g_AGG + (size_t)d * DIM + lane * 4;
    asm volatile("red.global.add.v4.f32 [%0], {%1, %2, %3, %4};"
                 :: "l"(o), "f"(m.x), "f"(m.y), "f"(m.z), "f"(m.w)
                 : "memory");
}

// ---------------- per-node finalize: relu(AGG*invcnt + Y_root + bias) -------
__global__ void finalize_k(const float* __restrict__ bias, float* __restrict__ Xout) {
    int idx = blockIdx.x * blockDim.x + threadIdx.x;  // N_ENT*DIM
    if (idx >= N_ENT * DIM) return;
    int n = idx >> 7, j = idx & 127;
    float v = g_AGG[idx] * g_CNT[n] + g_Y[(size_t)n * WN + NB * DIM + j] + bias[j];
    Xout[idx] = v > 0.0f ? v : 0.0f;
}

// ---------------- relation GCN (tiny) ---------------------------------------
__global__ void rel_gemm1(const float* __restrict__ DAD, const float* __restrict__ RC) {
    int idx = blockIdx.x * blockDim.x + threadIdx.x;  // NREL*DIM
    if (idx >= NREL * DIM) return;
    int i = idx >> 7, j = idx & 127;
    float s = 0.0f;
    for (int k = 0; k < NREL; k++) s += DAD[i * NREL + k] * RC[k * DIM + j];
    g_relT[idx] = s;
}

__global__ void rel_gemm2(const float* __restrict__ W) {
    int idx = blockIdx.x * blockDim.x + threadIdx.x;  // NREL*DIM
    if (idx >= NREL * DIM) return;
    int i = idx >> 7, j = idx & 127;
    float s = 0.0f;
    for (int k = 0; k < DIM; k++) s += g_relT[i * DIM + k] * W[k * DIM + j];
    g_relC[idx] = s > 0.0f ? s : 0.0f;
}

// ---------------- gated output gather ---------------------------------------
__global__ void out_kernel(const int* __restrict__ samples,
                           const float* __restrict__ ent_emb,
                           const float* __restrict__ rel_emb,
                           const float* __restrict__ gate_e,
                           const float* __restrict__ gate_r,
                           const float* __restrict__ Xfinal,
                           float* __restrict__ out) {
    int idx = blockIdx.x * blockDim.x + threadIdx.x;  // S_SAMP*DIM
    if (idx >= S_SAMP * DIM) return;
    int s = idx >> 7, j = idx & 127;
    float ge = 1.0f / (1.0f + expf(-gate_e[j]));
    float gr = 1.0f / (1.0f + expf(-gate_r[j]));
    int h = samples[s * 3 + 0];
    int r = samples[s * 3 + 1];
    int t = samples[s * 3 + 2];
    out[idx] = ge * ent_emb[(size_t)h * DIM + j] + (1.0f - ge) * Xfinal[(size_t)h * DIM + j];
    out[(size_t)S_SAMP * DIM + idx] =
        gr * rel_emb[(size_t)r * DIM + j] + (1.0f - gr) * g_relC[(size_t)r * DIM + j];
    out[2 * (size_t)S_SAMP * DIM + idx] =
        ge * ent_emb[(size_t)t * DIM + j] + (1.0f - ge) * Xfinal[(size_t)t * DIM + j];
}

// ---------------- launch -----------------------------------------------------
extern "C" void kernel_launch(void* const* d_in, const int* in_sizes, int n_in,
                              void* d_out, int out_size) {
    const int*   entity  = (const int*)d_in[0];
    const int*   eidx    = (const int*)d_in[1];
    const int*   etype   = (const int*)d_in[2];
    const float* enorm   = (const float*)d_in[3];
    const int*   samples = (const int*)d_in[4];
    const float* DAD     = (const float*)d_in[5];
    const float* ent_emb = (const float*)d_in[6];
    const float* rel_emb = (const float*)d_in[7];
    const float* ectx    = (const float*)d_in[8];
    const float* rctx    = (const float*)d_in[9];
    const float* rgw     = (const float*)d_in[10];
    const float* gate_e  = (const float*)d_in[11];
    const float* gate_r  = (const float*)d_in[12];
    const float* basis1  = (const float*)d_in[13];
    const float* att1    = (const float*)d_in[14];
    const float* root1   = (const float*)d_in[15];
    const float* bias1   = (const float*)d_in[16];
    const float* basis2  = (const float*)d_in[17];
    const float* att2    = (const float*)d_in[18];
    const float* root2   = (const float*)d_in[19];
    const float* bias2   = (const float*)d_in[20];
    float* out = (float*)d_out;

    const int* src = eidx;             // edge_index[0, :]
    const int* dst = eidx + E_EDGES;   // edge_index[1, :]

    float *pW, *pY, *pAGG, *pXB, *pXC;
    cudaGetSymbolAddress((void**)&pW,   g_Wcat);
    cudaGetSymbolAddress((void**)&pY,   g_Y);
    cudaGetSymbolAddress((void**)&pAGG, g_AGG);
    cudaGetSymbolAddress((void**)&pXB,  g_XB);
    cudaGetSymbolAddress((void**)&pXC,  g_XC);
    float* pCNT;
    cudaGetSymbolAddress((void**)&pCNT, g_CNT);

    const int TB = 256;
    const long long ND = (long long)N_ENT * DIM;

    // counts (shared by both layers) + zero accumulators
    zerok<<<512, TB>>>(pCNT, N_ENT);
    zerok<<<4096, TB>>>(pAGG, ND);
    count_k<<<(E_EDGES + TB - 1) / TB, TB>>>(dst);
    invcnt_k<<<(N_ENT + TB - 1) / TB, TB>>>();

    dim3 ggrid((N_ENT + 63) / 64, WN / 128);

    // ---- layer 1 (A-gather fused via entity indirection) ----
    build_wcat<<<(DIM * WN + TB - 1) / TB, TB>>>(basis1, root1);
    gemm128<<<ggrid, TB>>>(ectx, entity, pW, pY, N_ENT, WN, DIM);
    edge_msg<<<(E_EDGES * 32 + TB - 1) / TB, TB>>>(src, dst, etype, enorm, att1);
    finalize_k<<<(int)((ND + TB - 1) / TB), TB>>>(bias1, pXB);

    // ---- layer 2 ----
    zerok<<<4096, TB>>>(pAGG, ND);
    build_wcat<<<(DIM * WN + TB - 1) / TB, TB>>>(basis2, root2);
    gemm128<<<ggrid, TB>>>(pXB, (const int*)0, pW, pY, N_ENT, WN, DIM);
    edge_msg<<<(E_EDGES * 32 + TB - 1) / TB, TB>>>(src, dst, etype, enorm, att2);
    finalize_k<<<(int)((ND + TB - 1) / TB), TB>>>(bias2, pXC);

    // ---- relation GCN ----
    rel_gemm1<<<(NREL * DIM + TB - 1) / TB, TB>>>(DAD, rctx);
    rel_gemm2<<<(NREL * DIM + TB - 1) / TB, TB>>>(rgw);

    // ---- gated gather ----
    out_kernel<<<(S_SAMP * DIM + TB - 1) / TB, TB>>>(samples, ent_emb, rel_emb,
                                                     gate_e, gate_r, pXC, out);
}

// round 4
// speedup vs baseline: 1.1261x; 1.1261x over previous
#include <cuda_runtime.h>
#include <math.h>
#include <stdint.h>

#define N_ENT   50000
#define NREL    200
#define DIM     128
#define NB      4
#define E_EDGES 200000
#define S_SAMP  20000
#define WN      640   /* (NB+1)*DIM : [basis0..basis3 | root] */
#define KP      68    /* padded smem row stride (floats) */

// ---------------- scratch (device globals; no runtime allocation) ----------
__device__ float g_Wb[WN * DIM];                      // W^T hi  [640][128]
__device__ float g_Ws[WN * DIM];                      // W^T residual
__device__ float g_Xb[(size_t)N_ENT * DIM];           // X hi
__device__ float g_Xs[(size_t)N_ENT * DIM];           // X residual
__device__ float g_Y[(size_t)N_ENT * WN];             // 128 MB
__device__ float g_AGG[(size_t)N_ENT * DIM];          // 25.6 MB
__device__ float g_CNT[N_ENT];
__device__ float g_XF[(size_t)N_ENT * DIM];
__device__ float g_relT[NREL * DIM];
__device__ float g_relC[NREL * DIM];

// ---------------- helpers ---------------------------------------------------
__device__ __forceinline__ float tf32_hi(float x) {
    uint32_t r;
    asm("cvt.rna.tf32.f32 %0, %1;" : "=r"(r) : "f"(x));
    return __uint_as_float(r);
}

__device__ __forceinline__ void mma_tf32(float* d, const float* a, const float* b) {
    asm volatile(
        "mma.sync.aligned.m16n8k8.row.col.f32.tf32.tf32.f32 "
        "{%0,%1,%2,%3}, {%4,%5,%6,%7}, {%8,%9}, {%0,%1,%2,%3};"
        : "+f"(d[0]), "+f"(d[1]), "+f"(d[2]), "+f"(d[3])
        : "r"(__float_as_uint(a[0])), "r"(__float_as_uint(a[1])),
          "r"(__float_as_uint(a[2])), "r"(__float_as_uint(a[3])),
          "r"(__float_as_uint(b[0])), "r"(__float_as_uint(b[1])));
}

__global__ void zerok(float* p, long long n) {
    long long i = (long long)blockIdx.x * blockDim.x + threadIdx.x;
    long long stride = (long long)gridDim.x * blockDim.x;
    for (; i < n; i += stride) p[i] = 0.0f;
}

__global__ void count_k(const int* __restrict__ dst) {
    int i = blockIdx.x * blockDim.x + threadIdx.x;
    if (i < E_EDGES) atomicAdd(&g_CNT[dst[i]], 1.0f);
}

__global__ void invcnt_k() {
    int i = blockIdx.x * blockDim.x + threadIdx.x;
    if (i < N_ENT) {
        float c = g_CNT[i];
        c = c > 1.0f ? c : 1.0f;
        g_CNT[i] = 1.0f / c;
    }
}

// Build transposed split weights: Wt[c][k], c in [0,640), k in [0,128)
__global__ void build_w_split(const float* __restrict__ basis,
                              const float* __restrict__ root) {
    int idx = blockIdx.x * blockDim.x + threadIdx.x;  // WN*DIM
    if (idx >= WN * DIM) return;
    int c = idx >> 7, k = idx & 127;
    float w;
    if (c < NB * DIM) {
        int b = c >> 7;
        int j = c & 127;
        w = basis[((size_t)b * DIM + k) * DIM + j];
    } else {
        w = root[(size_t)k * DIM + (c - NB * DIM)];
    }
    float wb = tf32_hi(w);
    g_Wb[idx] = wb;
    g_Ws[idx] = w - wb;
}

// X0 = entity_context_tab[entity], split into tf32 hi/residual
__global__ void gather_split_x0(const int* __restrict__ entity,
                                const float* __restrict__ ectx) {
    int idx = blockIdx.x * blockDim.x + threadIdx.x;  // N_ENT*DIM
    if (idx >= N_ENT * DIM) return;
    int n = idx >> 7, j = idx & 127;
    float x = ectx[(size_t)entity[n] * DIM + j];
    float xb = tf32_hi(x);
    g_Xb[idx] = xb;
    g_Xs[idx] = x - xb;
}

// ---------------- 3xTF32 mma.sync GEMM: Y[M,640] = X[M,128] @ Wt^T ----------
// grid (ceil(M/128), 5), 256 threads (8 warps), warp tile 32x64, K chunks of 64.
__global__ void __launch_bounds__(256, 1)
gemm_mma(const float* __restrict__ Ab, const float* __restrict__ As, int M) {
    extern __shared__ float sm[];
    float* sAb = sm;                  // [128][KP]
    float* sAs = sAb + 128 * KP;
    float* sWb = sAs + 128 * KP;
    float* sWs = sWb + 128 * KP;

    int tid = threadIdx.x;
    int wid = tid >> 5;
    int lane = tid & 31;
    int lr = lane >> 2;               // 0..7
    int lc = lane & 3;                // 0..3
    int wm = (wid & 3) * 32;          // warp row offset in 128-tile
    int wn = (wid >> 2) * 64;         // warp col offset in 128-tile
    int m0 = blockIdx.x * 128;
    int n0 = blockIdx.y * 128;

    float acc[2][8][4];
#pragma unroll
    for (int i = 0; i < 2; i++)
#pragma unroll
        for (int j = 0; j < 8; j++)
#pragma unroll
            for (int q = 0; q < 4; q++) acc[i][j][q] = 0.0f;

    int r = tid >> 1;
    int q0 = (tid & 1) * 8;
    bool avalid = (m0 + r) < M;
    const float4 z4 = make_float4(0.f, 0.f, 0.f, 0.f);

    for (int kc = 0; kc < 2; kc++) {
        // ---- load tiles [128 rows x 64 cols] ----
        const float4* absrc = (const float4*)(Ab + (size_t)(avalid ? m0 + r : 0) * DIM + kc * 64);
        const float4* assrc = (const float4*)(As + (size_t)(avalid ? m0 + r : 0) * DIM + kc * 64);
        const float4* wbsrc = (const float4*)(g_Wb + (size_t)(n0 + r) * DIM + kc * 64);
        const float4* wssrc = (const float4*)(g_Ws + (size_t)(n0 + r) * DIM + kc * 64);
#pragma unroll
        for (int i = 0; i < 8; i++) {
            int q = q0 + i;
            *(float4*)(sAb + r * KP + q * 4) = avalid ? absrc[q] : z4;
            *(float4*)(sAs + r * KP + q * 4) = avalid ? assrc[q] : z4;
            *(float4*)(sWb + r * KP + q * 4) = wbsrc[q];
            *(float4*)(sWs + r * KP + q * 4) = wssrc[q];
        }
        __syncthreads();

#pragma unroll
        for (int k8 = 0; k8 < 8; k8++) {
            int kb = k8 * 8 + lc;
            float ab[2][4], av[2][4];
#pragma unroll
            for (int ma = 0; ma < 2; ma++) {
                int rr = wm + ma * 16 + lr;
                ab[ma][0] = sAb[rr * KP + kb];
                ab[ma][1] = sAb[(rr + 8) * KP + kb];
                ab[ma][2] = sAb[rr * KP + kb + 4];
                ab[ma][3] = sAb[(rr + 8) * KP + kb + 4];
                av[ma][0] = sAs[rr * KP + kb];
                av[ma][1] = sAs[(rr + 8) * KP + kb];
                av[ma][2] = sAs[rr * KP + kb + 4];
                av[ma][3] = sAs[(rr + 8) * KP + kb + 4];
            }
            float wb[8][2], ws[8][2];
#pragma unroll
            for (int na = 0; na < 8; na++) {
                int nn = wn + na * 8 + lr;
                wb[na][0] = sWb[nn * KP + kb];
                wb[na][1] = sWb[nn * KP + kb + 4];
                ws[na][0] = sWs[nn * KP + kb];
                ws[na][1] = sWs[nn * KP + kb + 4];
            }
#pragma unroll
            for (int ma = 0; ma < 2; ma++)
#pragma unroll
                for (int na = 0; na < 8; na++) {
                    mma_tf32(acc[ma][na], ab[ma], wb[na]);
                    mma_tf32(acc[ma][na], ab[ma], ws[na]);
                    mma_tf32(acc[ma][na], av[ma], wb[na]);
                }
        }
        __syncthreads();
    }

    // ---- epilogue ----
#pragma unroll
    for (int ma = 0; ma < 2; ma++) {
        int gr = m0 + wm + ma * 16 + lr;
#pragma unroll
        for (int na = 0; na < 8; na++) {
            int gc = n0 + wn + na * 8 + lc * 2;
            if (gr < M)
                *(float2*)(g_Y + (size_t)gr * WN + gc) =
                    make_float2(acc[ma][na][0], acc[ma][na][1]);
            if (gr + 8 < M)
                *(float2*)(g_Y + (size_t)(gr + 8) * WN + gc) =
                    make_float2(acc[ma][na][2], acc[ma][na][3]);
        }
    }
}

// ---------------- edge message scatter --------------------------------------
__global__ void edge_msg(const int* __restrict__ src, const int* __restrict__ dst,
                         const int* __restrict__ etype, const float* __restrict__ enorm,
                         const float* __restrict__ att) {
    int warp = (blockIdx.x * blockDim.x + threadIdx.x) >> 5;
    int lane = threadIdx.x & 31;
    if (warp >= E_EDGES) return;
    int s = src[warp];
    int d = dst[warp];
    int t = etype[warp];
    float nrm = enorm[warp];
    float4 a = *(const float4*)(att + (size_t)t * 4);
    a.x *= nrm; a.y *= nrm; a.z *= nrm; a.w *= nrm;

    const float4* y = (const float4*)(g_Y + (size_t)s * WN);
    float4 y0 = y[lane];
    float4 y1 = y[32 + lane];
    float4 y2 = y[64 + lane];
    float4 y3 = y[96 + lane];

    float4 m;
    m.x = a.x * y0.x + a.y * y1.x + a.z * y2.x + a.w * y3.x;
    m.y = a.x * y0.y + a.y * y1.y + a.z * y2.y + a.w * y3.y;
    m.z = a.x * y0.z + a.y * y1.z + a.z * y2.z + a.w * y3.z;
    m.w = a.x * y0.w + a.y * y1.w + a.z * y2.w + a.w * y3.w;

    float* o = g_AGG + (size_t)d * DIM + lane * 4;
    asm volatile("red.global.add.v4.f32 [%0], {%1, %2, %3, %4};"
                 :: "l"(o), "f"(m.x), "f"(m.y), "f"(m.z), "f"(m.w)
                 : "memory");
}

// ---------------- finalize ---------------------------------------------------
__global__ void finalize_split_k(const float* __restrict__ bias) {
    int idx = blockIdx.x * blockDim.x + threadIdx.x;
    if (idx >= N_ENT * DIM) return;
    int n = idx >> 7, j = idx & 127;
    float v = g_AGG[idx] * g_CNT[n] + g_Y[(size_t)n * WN + NB * DIM + j] + bias[j];
    v = v > 0.0f ? v : 0.0f;
    float vb = tf32_hi(v);
    g_Xb[idx] = vb;
    g_Xs[idx] = v - vb;
}

__global__ void finalize_full_k(const float* __restrict__ bias) {
    int idx = blockIdx.x * blockDim.x + threadIdx.x;
    if (idx >= N_ENT * DIM) return;
    int n = idx >> 7, j = idx & 127;
    float v = g_AGG[idx] * g_CNT[n] + g_Y[(size_t)n * WN + NB * DIM + j] + bias[j];
    g_XF[idx] = v > 0.0f ? v : 0.0f;
}

// ---------------- relation GCN (tiny) ----------------------------------------
__global__ void rel_gemm1(const float* __restrict__ DAD, const float* __restrict__ RC) {
    int idx = blockIdx.x * blockDim.x + threadIdx.x;
    if (idx >= NREL * DIM) return;
    int i = idx >> 7, j = idx & 127;
    float s = 0.0f;
    for (int k = 0; k < NREL; k++) s += DAD[i * NREL + k] * RC[k * DIM + j];
    g_relT[idx] = s;
}

__global__ void rel_gemm2(const float* __restrict__ W) {
    int idx = blockIdx.x * blockDim.x + threadIdx.x;
    if (idx >= NREL * DIM) return;
    int i = idx >> 7, j = idx & 127;
    float s = 0.0f;
    for (int k = 0; k < DIM; k++) s += g_relT[i * DIM + k] * W[k * DIM + j];
    g_relC[idx] = s > 0.0f ? s : 0.0f;
}

// ---------------- gated output gather ----------------------------------------
__global__ void out_kernel(const int* __restrict__ samples,
                           const float* __restrict__ ent_emb,
                           const float* __restrict__ rel_emb,
                           const float* __restrict__ gate_e,
                           const float* __restrict__ gate_r,
                           float* __restrict__ out) {
    int idx = blockIdx.x * blockDim.x + threadIdx.x;
    if (idx >= S_SAMP * DIM) return;
    int s = idx >> 7, j = idx & 127;
    float ge = 1.0f / (1.0f + expf(-gate_e[j]));
    float gr = 1.0f / (1.0f + expf(-gate_r[j]));
    int h = samples[s * 3 + 0];
    int r = samples[s * 3 + 1];
    int t = samples[s * 3 + 2];
    out[idx] = ge * ent_emb[(size_t)h * DIM + j] + (1.0f - ge) * g_XF[(size_t)h * DIM + j];
    out[(size_t)S_SAMP * DIM + idx] =
        gr * rel_emb[(size_t)r * DIM + j] + (1.0f - gr) * g_relC[(size_t)r * DIM + j];
    out[2 * (size_t)S_SAMP * DIM + idx] =
        ge * ent_emb[(size_t)t * DIM + j] + (1.0f - ge) * g_XF[(size_t)t * DIM + j];
}

// ---------------- launch -----------------------------------------------------
extern "C" void kernel_launch(void* const* d_in, const int* in_sizes, int n_in,
                              void* d_out, int out_size) {
    const int*   entity  = (const int*)d_in[0];
    const int*   eidx    = (const int*)d_in[1];
    const int*   etype   = (const int*)d_in[2];
    const float* enorm   = (const float*)d_in[3];
    const int*   samples = (const int*)d_in[4];
    const float* DAD     = (const float*)d_in[5];
    const float* ent_emb = (const float*)d_in[6];
    const float* rel_emb = (const float*)d_in[7];
    const float* ectx    = (const float*)d_in[8];
    const float* rctx    = (const float*)d_in[9];
    const float* rgw     = (const float*)d_in[10];
    const float* gate_e  = (const float*)d_in[11];
    const float* gate_r  = (const float*)d_in[12];
    const float* basis1  = (const float*)d_in[13];
    const float* att1    = (const float*)d_in[14];
    const float* root1   = (const float*)d_in[15];
    const float* bias1   = (const float*)d_in[16];
    const float* basis2  = (const float*)d_in[17];
    const float* att2    = (const float*)d_in[18];
    const float* root2   = (const float*)d_in[19];
    const float* bias2   = (const float*)d_in[20];
    float* out = (float*)d_out;

    const int* src = eidx;
    const int* dst = eidx + E_EDGES;

    float *pAGG, *pCNT, *pXb, *pXs;
    cudaGetSymbolAddress((void**)&pAGG, g_AGG);
    cudaGetSymbolAddress((void**)&pCNT, g_CNT);
    cudaGetSymbolAddress((void**)&pXb,  g_Xb);
    cudaGetSymbolAddress((void**)&pXs,  g_Xs);

    const int SMEM_SZ = 4 * 128 * KP * 4;  // 139264 B
    static bool attr_set = false;
    if (!attr_set) {
        cudaFuncSetAttribute(gemm_mma, cudaFuncAttributeMaxDynamicSharedMemorySize, SMEM_SZ);
        attr_set = true;
    }

    const int TB = 256;
    const long long ND = (long long)N_ENT * DIM;
    dim3 ggrid((N_ENT + 127) / 128, WN / 128);

    // counts (shared by both layers) + zero accumulators
    zerok<<<512, TB>>>(pCNT, N_ENT);
    zerok<<<4096, TB>>>(pAGG, ND);
    count_k<<<(E_EDGES + TB - 1) / TB, TB>>>(dst);
    invcnt_k<<<(N_ENT + TB - 1) / TB, TB>>>();

    // ---- layer 1 ----
    build_w_split<<<(WN * DIM + TB - 1) / TB, TB>>>(basis1, root1);
    gather_split_x0<<<(int)((ND + TB - 1) / TB), TB>>>(entity, ectx);
    gemm_mma<<<ggrid, TB, SMEM_SZ>>>(pXb, pXs, N_ENT);
    edge_msg<<<(E_EDGES * 32 + TB - 1) / TB, TB>>>(src, dst, etype, enorm, att1);
    finalize_split_k<<<(int)((ND + TB - 1) / TB), TB>>>(bias1);

    // ---- layer 2 ----
    zerok<<<4096, TB>>>(pAGG, ND);
    build_w_split<<<(WN * DIM + TB - 1) / TB, TB>>>(basis2, root2);
    gemm_mma<<<ggrid, TB, SMEM_SZ>>>(pXb, pXs, N_ENT);
    edge_msg<<<(E_EDGES * 32 + TB - 1) / TB, TB>>>(src, dst, etype, enorm, att2);
    finalize_full_k<<<(int)((ND + TB - 1) / TB), TB>>>(bias2);

    // ---- relation GCN ----
    rel_gemm1<<<(NREL * DIM + TB - 1) / TB, TB>>>(DAD, rctx);
    rel_gemm2<<<(NREL * DIM + TB - 1) / TB, TB>>>(rgw);

    // ---- gated gather ----
    out_kernel<<<(S_SAMP * DIM + TB - 1) / TB, TB>>>(samples, ent_emb, rel_emb,
                                                     gate_e, gate_r, out);
}

// round 5
// speedup vs baseline: 2.0914x; 1.8572x over previous
#include <cuda_runtime.h>
#include <math.h>
#include <stdint.h>

#define N_ENT   50000
#define NREL    200
#define DIM     128
#define NB      4
#define E_EDGES 200000
#define S_SAMP  20000
#define WN      640   /* (NB+1)*DIM : [basis0..basis3 | root] */
#define MTILES  391   /* ceil(50000/128) */
#define APAD    132   /* A smem row stride (floats), full K=128 + pad */
#define WPAD    36    /* W smem row stride (floats), chunk 32 + pad  */

// ---------------- scratch (device globals; no runtime allocation) ----------
__device__ float g_Wb[WN * DIM];                      // W^T hi  [640][128]
__device__ float g_Ws[WN * DIM];                      // W^T residual
__device__ float g_Xb[(size_t)N_ENT * DIM];           // X hi
__device__ float g_Xs[(size_t)N_ENT * DIM];           // X residual
__device__ float g_Y[(size_t)N_ENT * WN];             // 128 MB
__device__ float g_AGG[(size_t)N_ENT * DIM];          // 25.6 MB
__device__ float g_CNT[N_ENT];
__device__ float g_XF[(size_t)N_ENT * DIM];
__device__ float g_relT[NREL * DIM];
__device__ float g_relC[NREL * DIM];

// ---------------- helpers ---------------------------------------------------
__device__ __forceinline__ uint32_t smem_u32(const void* p) {
    uint32_t a;
    asm("{ .reg .u64 t; cvta.to.shared.u64 t, %1; cvt.u32.u64 %0, t; }"
        : "=r"(a) : "l"(p));
    return a;
}
__device__ __forceinline__ float tf32_hi(float x) {
    uint32_t r;
    asm("cvt.rna.tf32.f32 %0, %1;" : "=r"(r) : "f"(x));
    return __uint_as_float(r);
}
__device__ __forceinline__ void cp16(uint32_t dst_s, const float* src) {
    asm volatile("cp.async.cg.shared.global [%0], [%1], 16;"
                 :: "r"(dst_s), "l"(src));
}
#define CP_COMMIT() asm volatile("cp.async.commit_group;" ::: "memory")
#define CP_WAIT1()  asm volatile("cp.async.wait_group 1;" ::: "memory")
#define CP_WAIT0()  asm volatile("cp.async.wait_group 0;" ::: "memory")

__device__ __forceinline__ void mma_tf32(float* d, const uint32_t* a, const uint32_t* b) {
    asm volatile(
        "mma.sync.aligned.m16n8k8.row.col.f32.tf32.tf32.f32 "
        "{%0,%1,%2,%3}, {%4,%5,%6,%7}, {%8,%9}, {%0,%1,%2,%3};"
        : "+f"(d[0]), "+f"(d[1]), "+f"(d[2]), "+f"(d[3])
        : "r"(a[0]), "r"(a[1]), "r"(a[2]), "r"(a[3]),
          "r"(b[0]), "r"(b[1]));
}
#define LDSM4(r0, r1, r2, r3, addr) \
    asm volatile("ldmatrix.sync.aligned.m8n8.x4.shared.b16 {%0,%1,%2,%3}, [%4];" \
                 : "=r"(r0), "=r"(r1), "=r"(r2), "=r"(r3) : "r"(addr))

__global__ void zerok(float* p, long long n) {
    long long i = (long long)blockIdx.x * blockDim.x + threadIdx.x;
    long long stride = (long long)gridDim.x * blockDim.x;
    for (; i < n; i += stride) p[i] = 0.0f;
}

__global__ void count_k(const int* __restrict__ dst) {
    int i = blockIdx.x * blockDim.x + threadIdx.x;
    if (i < E_EDGES) atomicAdd(&g_CNT[dst[i]], 1.0f);
}

__global__ void invcnt_k() {
    int i = blockIdx.x * blockDim.x + threadIdx.x;
    if (i < N_ENT) {
        float c = g_CNT[i];
        c = c > 1.0f ? c : 1.0f;
        g_CNT[i] = 1.0f / c;
    }
}

// Build transposed split weights: Wt[c][k], c in [0,640), k in [0,128)
__global__ void build_w_split(const float* __restrict__ basis,
                              const float* __restrict__ root) {
    int idx = blockIdx.x * blockDim.x + threadIdx.x;  // WN*DIM
    if (idx >= WN * DIM) return;
    int c = idx >> 7, k = idx & 127;
    float w;
    if (c < NB * DIM) {
        int b = c >> 7;
        int j = c & 127;
        w = basis[((size_t)b * DIM + k) * DIM + j];
    } else {
        w = root[(size_t)k * DIM + (c - NB * DIM)];
    }
    float wb = tf32_hi(w);
    g_Wb[idx] = wb;
    g_Ws[idx] = w - wb;
}

// X0 = entity_context_tab[entity], split into tf32 hi/residual
__global__ void gather_split_x0(const int* __restrict__ entity,
                                const float* __restrict__ ectx) {
    int idx = blockIdx.x * blockDim.x + threadIdx.x;  // N_ENT*DIM
    if (idx >= N_ENT * DIM) return;
    int n = idx >> 7, j = idx & 127;
    float x = ectx[(size_t)entity[n] * DIM + j];
    float xb = tf32_hi(x);
    g_Xb[idx] = xb;
    g_Xs[idx] = x - xb;
}

// ---------------- 3xTF32 ldmatrix GEMM: Y[M,640] = X[M,128] @ Wt^T ----------
// Persistent: grid 148, 256 thr (8 warps 4m x 2n, warp tile 32x64).
// A (both splits, full K) resident in smem; W streamed in k-chunks of 32,
// double-buffered with cp.async.
//
// smem: sA[2][128][APAD]  = 135168 B
//       sW[2][2][128][WPAD] (buf, split) = 73728 B        total 208896 B
#define SA_FLOATS (2 * 128 * APAD)
#define SW_BUF_FLOATS (2 * 128 * WPAD)
#define SMEM_SZ ((SA_FLOATS + 2 * SW_BUF_FLOATS) * 4)

__device__ __forceinline__ void load_w_chunk(uint32_t sW_u, int buf, int nb, int kc,
                                             int tid) {
    int n = tid >> 1;            // 0..127
    int q = tid & 1;             // half-row: 4 float4 each
    const float* srcb = g_Wb + (size_t)(nb * 128 + n) * DIM + kc * 32 + q * 16;
    const float* srcs = g_Ws + (size_t)(nb * 128 + n) * DIM + kc * 32 + q * 16;
    uint32_t db = sW_u + (uint32_t)(((buf * 2 + 0) * 128 + n) * WPAD + q * 16) * 4;
    uint32_t ds = sW_u + (uint32_t)(((buf * 2 + 1) * 128 + n) * WPAD + q * 16) * 4;
#pragma unroll
    for (int i = 0; i < 4; i++) {
        cp16(db + i * 16, srcb + i * 4);
        cp16(ds + i * 16, srcs + i * 4);
    }
}

__global__ void __launch_bounds__(256, 1)
gemm_mma(const float* __restrict__ Ab, const float* __restrict__ As, int M) {
    extern __shared__ float sm[];
    uint32_t sA_u = smem_u32(sm);
    uint32_t sW_u = sA_u + SA_FLOATS * 4;

    int tid = threadIdx.x;
    int wid = tid >> 5;
    int lane = tid & 31;
    int lc = lane & 3;
    int wm = (wid & 3) * 32;
    int wn = (wid >> 2) * 64;

    // ldmatrix per-thread address components (derived from validated R4 mapping)
    int a_r = (lane & 7) + (lane & 8);          // row offset within 16-row tile
    int a_c = (lane >> 4) << 2;                 // 0 or 4 (k quadrant)
    int w_r = (lane & 7) + ((lane >> 4) << 3);  // n offset within 16-n pair
    int w_c = ((lane >> 3) & 1) << 2;           // 0 or 4 (k quadrant)

    for (int mt = blockIdx.x; mt < MTILES; mt += gridDim.x) {
        int m0 = mt * 128;

        // ---- issue A loads (cp.async), both splits, full K ----
        {
            int r = tid >> 1, h = tid & 1;
            int gr = m0 + r;
            if (gr >= M) gr = 0;   // ghost rows: load row 0 (finite, never used)
            const float* pb = Ab + (size_t)gr * DIM + h * 64;
            const float* ps = As + (size_t)gr * DIM + h * 64;
            uint32_t db = sA_u + (uint32_t)(r * APAD + h * 64) * 4;
            uint32_t ds = db + (uint32_t)(128 * APAD) * 4;
#pragma unroll
            for (int i = 0; i < 16; i++) {
                cp16(db + i * 16, pb + i * 4);
                cp16(ds + i * 16, ps + i * 4);
            }
        }
        // first W chunk (nb=0, kc=0) into buf 0, same group as A
        load_w_chunk(sW_u, 0, 0, 0, tid);
        CP_COMMIT();

        int buf = 0;
        for (int nb = 0; nb < 5; nb++) {
            float acc[2][8][4];
#pragma unroll
            for (int i = 0; i < 2; i++)
#pragma unroll
                for (int j = 0; j < 8; j++)
#pragma unroll
                    for (int q = 0; q < 4; q++) acc[i][j][q] = 0.0f;

            for (int kc = 0; kc < 4; kc++) {
                int t = nb * 4 + kc;
                if (t + 1 < 20) {
                    load_w_chunk(sW_u, buf ^ 1, (t + 1) >> 2, (t + 1) & 3, tid);
                    CP_COMMIT();
                    CP_WAIT1();
                } else {
                    CP_WAIT0();
                }
                __syncthreads();

                uint32_t sWb = sW_u + (uint32_t)((buf * 2 + 0) * 128 * WPAD) * 4;
                uint32_t sWs = sW_u + (uint32_t)((buf * 2 + 1) * 128 * WPAD) * 4;
#pragma unroll
                for (int k8 = 0; k8 < 4; k8++) {
                    int kb = kc * 32 + k8 * 8;   // A col (global K)
                    int kw = k8 * 8;             // W col (within chunk)

                    uint32_t ab[2][4], av[2][4];
#pragma unroll
                    for (int ma = 0; ma < 2; ma++) {
                        uint32_t ad = sA_u +
                            (uint32_t)(((wm + ma * 16 + a_r) * APAD) + kb + a_c) * 4;
                        LDSM4(ab[ma][0], ab[ma][1], ab[ma][2], ab[ma][3], ad);
                        ad += (uint32_t)(128 * APAD) * 4;
                        LDSM4(av[ma][0], av[ma][1], av[ma][2], av[ma][3], ad);
                    }
                    uint32_t wb[8][2], ws[8][2];
#pragma unroll
                    for (int p = 0; p < 4; p++) {
                        uint32_t off = (uint32_t)(((wn + p * 16 + w_r) * WPAD) + kw + w_c) * 4;
                        LDSM4(wb[2 * p][0], wb[2 * p][1], wb[2 * p + 1][0], wb[2 * p + 1][1],
                              sWb + off);
                        LDSM4(ws[2 * p][0], ws[2 * p][1], ws[2 * p + 1][0], ws[2 * p + 1][1],
                              sWs + off);
                    }
#pragma unroll
                    for (int ma = 0; ma < 2; ma++)
#pragma unroll
                        for (int na = 0; na < 8; na++) {
                            mma_tf32(acc[ma][na], ab[ma], wb[na]);
                            mma_tf32(acc[ma][na], ab[ma], ws[na]);
                            mma_tf32(acc[ma][na], av[ma], wb[na]);
                        }
                }
                __syncthreads();
                buf ^= 1;
            }

            // ---- epilogue for this n-block ----
            int lr = lane >> 2;
#pragma unroll
            for (int ma = 0; ma < 2; ma++) {
                int gr = m0 + wm + ma * 16 + lr;
#pragma unroll
                for (int na = 0; na < 8; na++) {
                    int gc = nb * 128 + wn + na * 8 + lc * 2;
                    if (gr < M)
                        *(float2*)(g_Y + (size_t)gr * WN + gc) =
                            make_float2(acc[ma][na][0], acc[ma][na][1]);
                    if (gr + 8 < M)
                        *(float2*)(g_Y + (size_t)(gr + 8) * WN + gc) =
                            make_float2(acc[ma][na][2], acc[ma][na][3]);
                }
            }
        }
    }
}

// ---------------- edge message scatter --------------------------------------
__global__ void edge_msg(const int* __restrict__ src, const int* __restrict__ dst,
                         const int* __restrict__ etype, const float* __restrict__ enorm,
                         const float* __restrict__ att) {
    int warp = (blockIdx.x * blockDim.x + threadIdx.x) >> 5;
    int lane = threadIdx.x & 31;
    if (warp >= E_EDGES) return;
    int s = src[warp];
    int d = dst[warp];
    int t = etype[warp];
    float nrm = enorm[warp];
    float4 a = *(const float4*)(att + (size_t)t * 4);
    a.x *= nrm; a.y *= nrm; a.z *= nrm; a.w *= nrm;

    const float4* y = (const float4*)(g_Y + (size_t)s * WN);
    float4 y0 = y[lane];
    float4 y1 = y[32 + lane];
    float4 y2 = y[64 + lane];
    float4 y3 = y[96 + lane];

    float4 m;
    m.x = a.x * y0.x + a.y * y1.x + a.z * y2.x + a.w * y3.x;
    m.y = a.x * y0.y + a.y * y1.y + a.z * y2.y + a.w * y3.y;
    m.z = a.x * y0.z + a.y * y1.z + a.z * y2.z + a.w * y3.z;
    m.w = a.x * y0.w + a.y * y1.w + a.z * y2.w + a.w * y3.w;

    float* o = g_AGG + (size_t)d * DIM + lane * 4;
    asm volatile("red.global.add.v4.f32 [%0], {%1, %2, %3, %4};"
                 :: "l"(o), "f"(m.x), "f"(m.y), "f"(m.z), "f"(m.w)
                 : "memory");
}

// ---------------- finalize ---------------------------------------------------
__global__ void finalize_split_k(const float* __restrict__ bias) {
    int idx = blockIdx.x * blockDim.x + threadIdx.x;
    if (idx >= N_ENT * DIM) return;
    int n = idx >> 7, j = idx & 127;
    float v = g_AGG[idx] * g_CNT[n] + g_Y[(size_t)n * WN + NB * DIM + j] + bias[j];
    v = v > 0.0f ? v : 0.0f;
    float vb = tf32_hi(v);
    g_Xb[idx] = vb;
    g_Xs[idx] = v - vb;
}

__global__ void finalize_full_k(const float* __restrict__ bias) {
    int idx = blockIdx.x * blockDim.x + threadIdx.x;
    if (idx >= N_ENT * DIM) return;
    int n = idx >> 7, j = idx & 127;
    float v = g_AGG[idx] * g_CNT[n] + g_Y[(size_t)n * WN + NB * DIM + j] + bias[j];
    g_XF[idx] = v > 0.0f ? v : 0.0f;
}

// ---------------- relation GCN (tiny) ----------------------------------------
__global__ void rel_gemm1(const float* __restrict__ DAD, const float* __restrict__ RC) {
    int idx = blockIdx.x * blockDim.x + threadIdx.x;
    if (idx >= NREL * DIM) return;
    int i = idx >> 7, j = idx & 127;
    float s = 0.0f;
    for (int k = 0; k < NREL; k++) s += DAD[i * NREL + k] * RC[k * DIM + j];
    g_relT[idx] = s;
}

__global__ void rel_gemm2(const float* __restrict__ W) {
    int idx = blockIdx.x * blockDim.x + threadIdx.x;
    if (idx >= NREL * DIM) return;
    int i = idx >> 7, j = idx & 127;
    float s = 0.0f;
    for (int k = 0; k < DIM; k++) s += g_relT[i * DIM + k] * W[k * DIM + j];
    g_relC[idx] = s > 0.0f ? s : 0.0f;
}

// ---------------- gated output gather ----------------------------------------
__global__ void out_kernel(const int* __restrict__ samples,
                           const float* __restrict__ ent_emb,
                           const float* __restrict__ rel_emb,
                           const float* __restrict__ gate_e,
                           const float* __restrict__ gate_r,
                           float* __restrict__ out) {
    int idx = blockIdx.x * blockDim.x + threadIdx.x;
    if (idx >= S_SAMP * DIM) return;
    int s = idx >> 7, j = idx & 127;
    float ge = 1.0f / (1.0f + expf(-gate_e[j]));
    float gr = 1.0f / (1.0f + expf(-gate_r[j]));
    int h = samples[s * 3 + 0];
    int r = samples[s * 3 + 1];
    int t = samples[s * 3 + 2];
    out[idx] = ge * ent_emb[(size_t)h * DIM + j] + (1.0f - ge) * g_XF[(size_t)h * DIM + j];
    out[(size_t)S_SAMP * DIM + idx] =
        gr * rel_emb[(size_t)r * DIM + j] + (1.0f - gr) * g_relC[(size_t)r * DIM + j];
    out[2 * (size_t)S_SAMP * DIM + idx] =
        ge * ent_emb[(size_t)t * DIM + j] + (1.0f - ge) * g_XF[(size_t)t * DIM + j];
}

// ---------------- launch -----------------------------------------------------
extern "C" void kernel_launch(void* const* d_in, const int* in_sizes, int n_in,
                              void* d_out, int out_size) {
    const int*   entity  = (const int*)d_in[0];
    const int*   eidx    = (const int*)d_in[1];
    const int*   etype   = (const int*)d_in[2];
    const float* enorm   = (const float*)d_in[3];
    const int*   samples = (const int*)d_in[4];
    const float* DAD     = (const float*)d_in[5];
    const float* ent_emb = (const float*)d_in[6];
    const float* rel_emb = (const float*)d_in[7];
    const float* ectx    = (const float*)d_in[8];
    const float* rctx    = (const float*)d_in[9];
    const float* rgw     = (const float*)d_in[10];
    const float* gate_e  = (const float*)d_in[11];
    const float* gate_r  = (const float*)d_in[12];
    const float* basis1  = (const float*)d_in[13];
    const float* att1    = (const float*)d_in[14];
    const float* root1   = (const float*)d_in[15];
    const float* bias1   = (const float*)d_in[16];
    const float* basis2  = (const float*)d_in[17];
    const float* att2    = (const float*)d_in[18];
    const float* root2   = (const float*)d_in[19];
    const float* bias2   = (const float*)d_in[20];
    float* out = (float*)d_out;

    const int* src = eidx;
    const int* dst = eidx + E_EDGES;

    float *pAGG, *pCNT, *pXb, *pXs;
    cudaGetSymbolAddress((void**)&pAGG, g_AGG);
    cudaGetSymbolAddress((void**)&pCNT, g_CNT);
    cudaGetSymbolAddress((void**)&pXb,  g_Xb);
    cudaGetSymbolAddress((void**)&pXs,  g_Xs);

    static bool attr_set = false;
    if (!attr_set) {
        cudaFuncSetAttribute(gemm_mma, cudaFuncAttributeMaxDynamicSharedMemorySize, SMEM_SZ);
        attr_set = true;
    }

    const int TB = 256;
    const long long ND = (long long)N_ENT * DIM;

    // counts (shared by both layers) + zero accumulators
    zerok<<<512, TB>>>(pCNT, N_ENT);
    zerok<<<4096, TB>>>(pAGG, ND);
    count_k<<<(E_EDGES + TB - 1) / TB, TB>>>(dst);
    invcnt_k<<<(N_ENT + TB - 1) / TB, TB>>>();

    // ---- layer 1 ----
    build_w_split<<<(WN * DIM + TB - 1) / TB, TB>>>(basis1, root1);
    gather_split_x0<<<(int)((ND + TB - 1) / TB), TB>>>(entity, ectx);
    gemm_mma<<<148, TB, SMEM_SZ>>>(pXb, pXs, N_ENT);
    edge_msg<<<(E_EDGES * 32 + TB - 1) / TB, TB>>>(src, dst, etype, enorm, att1);
    finalize_split_k<<<(int)((ND + TB - 1) / TB), TB>>>(bias1);

    // ---- layer 2 ----
    zerok<<<4096, TB>>>(pAGG, ND);
    build_w_split<<<(WN * DIM + TB - 1) / TB, TB>>>(basis2, root2);
    gemm_mma<<<148, TB, SMEM_SZ>>>(pXb, pXs, N_ENT);
    edge_msg<<<(E_EDGES * 32 + TB - 1) / TB, TB>>>(src, dst, etype, enorm, att2);
    finalize_full_k<<<(int)((ND + TB - 1) / TB), TB>>>(bias2);

    // ---- relation GCN ----
    rel_gemm1<<<(NREL * DIM + TB - 1) / TB, TB>>>(DAD, rctx);
    rel_gemm2<<<(NREL * DIM + TB - 1) / TB, TB>>>(rgw);

    // ---- gated gather ----
    out_kernel<<<(S_SAMP * DIM + TB - 1) / TB, TB>>>(samples, ent_emb, rel_emb,
                                                     gate_e, gate_r, out);
}

// round 6
// speedup vs baseline: 2.8008x; 1.3392x over previous
#include <cuda_runtime.h>
#include <cuda_bf16.h>
#include <math.h>
#include <stdint.h>

#define N_ENT   50000
#define NREL    200
#define DIM     128
#define NB      4
#define E_EDGES 200000
#define S_SAMP  20000
#define WN      640   /* (NB+1)*DIM : [basis0..basis3 | root] */
#define MTILES  391   /* ceil(50000/128) */
#define AH      136   /* A smem row stride (halfs): K=128 + pad */
#define WH      72    /* W smem row stride (halfs): chunk 64 + pad */

// ---------------- scratch (device globals; no runtime allocation) ----------
__device__ __nv_bfloat16 g_Wbh[WN * DIM];             // W^T hi  [640][128]
__device__ __nv_bfloat16 g_Wsh[WN * DIM];             // W^T residual
__device__ __nv_bfloat16 g_Xbh[(size_t)N_ENT * DIM];  // X hi
__device__ __nv_bfloat16 g_Xsh[(size_t)N_ENT * DIM];  // X residual
__device__ float g_Y[(size_t)N_ENT * WN];             // 128 MB
__device__ float g_AGG[(size_t)N_ENT * DIM];          // 25.6 MB
__device__ float g_CNT[N_ENT];
__device__ float g_XF[(size_t)N_ENT * DIM];
__device__ float g_relT[NREL * DIM];
__device__ float g_relC[NREL * DIM];

// ---------------- helpers ---------------------------------------------------
__device__ __forceinline__ uint32_t smem_u32(const void* p) {
    uint32_t a;
    asm("{ .reg .u64 t; cvta.to.shared.u64 t, %1; cvt.u32.u64 %0, t; }"
        : "=r"(a) : "l"(p));
    return a;
}
__device__ __forceinline__ void cp16(uint32_t dst_s, const void* src) {
    asm volatile("cp.async.cg.shared.global [%0], [%1], 16;"
                 :: "r"(dst_s), "l"(src));
}
#define CP_COMMIT() asm volatile("cp.async.commit_group;" ::: "memory")
#define CP_WAIT1()  asm volatile("cp.async.wait_group 1;" ::: "memory")
#define CP_WAIT0()  asm volatile("cp.async.wait_group 0;" ::: "memory")

__device__ __forceinline__ void mma_bf16(float* d, const uint32_t* a,
                                         uint32_t b0, uint32_t b1) {
    asm volatile(
        "mma.sync.aligned.m16n8k16.row.col.f32.bf16.bf16.f32 "
        "{%0,%1,%2,%3}, {%4,%5,%6,%7}, {%8,%9}, {%0,%1,%2,%3};"
        : "+f"(d[0]), "+f"(d[1]), "+f"(d[2]), "+f"(d[3])
        : "r"(a[0]), "r"(a[1]), "r"(a[2]), "r"(a[3]), "r"(b0), "r"(b1));
}
#define LDSM4(r0, r1, r2, r3, addr) \
    asm volatile("ldmatrix.sync.aligned.m8n8.x4.shared.b16 {%0,%1,%2,%3}, [%4];" \
                 : "=r"(r0), "=r"(r1), "=r"(r2), "=r"(r3) : "r"(addr))

// zero CNT and AGG in one launch
__global__ void zero_init() {
    long long n = (long long)N_ENT * DIM + N_ENT;
    long long i = (long long)blockIdx.x * blockDim.x + threadIdx.x;
    long long stride = (long long)gridDim.x * blockDim.x;
    for (; i < n; i += stride) {
        if (i < (long long)N_ENT * DIM) g_AGG[i] = 0.0f;
        else g_CNT[i - (long long)N_ENT * DIM] = 0.0f;
    }
}

__global__ void count_k(const int* __restrict__ dst) {
    int i = blockIdx.x * blockDim.x + threadIdx.x;
    if (i < E_EDGES) atomicAdd(&g_CNT[dst[i]], 1.0f);
}

__global__ void invcnt_k() {
    int i = blockIdx.x * blockDim.x + threadIdx.x;
    if (i < N_ENT) {
        float c = g_CNT[i];
        c = c > 1.0f ? c : 1.0f;
        g_CNT[i] = 1.0f / c;
    }
}

// Build transposed split weights: Wt[c][k], c in [0,640), k in [0,128)
__global__ void build_w_split(const float* __restrict__ basis,
                              const float* __restrict__ root) {
    int idx = blockIdx.x * blockDim.x + threadIdx.x;  // WN*DIM
    if (idx >= WN * DIM) return;
    int c = idx >> 7, k = idx & 127;
    float w;
    if (c < NB * DIM) {
        int b = c >> 7;
        int j = c & 127;
        w = basis[((size_t)b * DIM + k) * DIM + j];
    } else {
        w = root[(size_t)k * DIM + (c - NB * DIM)];
    }
    __nv_bfloat16 hb = __float2bfloat16_rn(w);
    g_Wbh[idx] = hb;
    g_Wsh[idx] = __float2bfloat16_rn(w - __bfloat162float(hb));
}

// X0 = entity_context_tab[entity], split into bf16 hi/residual
__global__ void gather_split_x0(const int* __restrict__ entity,
                                const float* __restrict__ ectx) {
    int idx = blockIdx.x * blockDim.x + threadIdx.x;  // N_ENT*DIM
    if (idx >= N_ENT * DIM) return;
    int n = idx >> 7, j = idx & 127;
    float x = ectx[(size_t)entity[n] * DIM + j];
    __nv_bfloat16 hb = __float2bfloat16_rn(x);
    g_Xbh[idx] = hb;
    g_Xsh[idx] = __float2bfloat16_rn(x - __bfloat162float(hb));
}

// ---------------- 3xBF16 ldmatrix GEMM: Y[M,640] = X[M,128] @ Wt^T ----------
// Persistent grid 148, 256 thr (8 warps 4m x 2n, warp tile 32x64).
// A (both splits, full K) resident in smem bf16; W streamed in k-chunks of 64,
// double-buffered with cp.async.
#define SA_HALFS    (2 * 128 * AH)        /* 34816 halfs = 69632 B */
#define SWBUF_HALFS (2 * 128 * WH)        /* 18432 halfs = 36864 B per buf */
#define SMEM_SZ     ((SA_HALFS + 2 * SWBUF_HALFS) * 2)   /* 143360 B */

__device__ __forceinline__ void load_w_chunk(uint32_t sW_u, int buf, int nb, int kc,
                                             int tid) {
    int n = tid >> 1;            // 0..127
    int q = tid & 1;             // half-row: 32 halfs each
    const __nv_bfloat16* srcb = g_Wbh + (size_t)(nb * 128 + n) * DIM + kc * 64 + q * 32;
    const __nv_bfloat16* srcs = g_Wsh + (size_t)(nb * 128 + n) * DIM + kc * 64 + q * 32;
    uint32_t db = sW_u + (uint32_t)(buf * SWBUF_HALFS + 0 * 128 * WH + n * WH + q * 32) * 2;
    uint32_t ds = sW_u + (uint32_t)(buf * SWBUF_HALFS + 1 * 128 * WH + n * WH + q * 32) * 2;
#pragma unroll
    for (int i = 0; i < 4; i++) {
        cp16(db + i * 16, srcb + i * 8);
        cp16(ds + i * 16, srcs + i * 8);
    }
}

__global__ void __launch_bounds__(256, 1)
gemm_mma(int M) {
    extern __shared__ char smraw[];
    uint32_t sA_u = smem_u32(smraw);
    uint32_t sW_u = sA_u + SA_HALFS * 2;

    int tid = threadIdx.x;
    int wid = tid >> 5;
    int lane = tid & 31;
    int wm = (wid & 3) * 32;
    int wn = (wid >> 2) * 64;

    // ldmatrix address components (b16): row = lane&15, col-quad = (lane>>4)*8
    int f_r = lane & 15;
    int f_c = (lane >> 4) << 3;

    for (int mt = blockIdx.x; mt < MTILES; mt += gridDim.x) {
        int m0 = mt * 128;

        // ---- issue A loads (cp.async), both splits, full K ----
        {
            int r = tid >> 1, h = tid & 1;
            int gr = m0 + r;
            if (gr >= M) gr = 0;   // ghost rows: finite, never stored
            const __nv_bfloat16* pb = g_Xbh + (size_t)gr * DIM + h * 64;
            const __nv_bfloat16* ps = g_Xsh + (size_t)gr * DIM + h * 64;
            uint32_t db = sA_u + (uint32_t)(r * AH + h * 64) * 2;
            uint32_t ds = db + (uint32_t)(128 * AH) * 2;
#pragma unroll
            for (int i = 0; i < 8; i++) {
                cp16(db + i * 16, pb + i * 8);
                cp16(ds + i * 16, ps + i * 8);
            }
        }
        load_w_chunk(sW_u, 0, 0, 0, tid);
        CP_COMMIT();

        int buf = 0;
        for (int nb = 0; nb < 5; nb++) {
            float acc[2][8][4];
#pragma unroll
            for (int i = 0; i < 2; i++)
#pragma unroll
                for (int j = 0; j < 8; j++)
#pragma unroll
                    for (int q = 0; q < 4; q++) acc[i][j][q] = 0.0f;

            for (int kc = 0; kc < 2; kc++) {
                int t = nb * 2 + kc;
                if (t + 1 < 10) {
                    load_w_chunk(sW_u, buf ^ 1, (t + 1) >> 1, (t + 1) & 1, tid);
                    CP_COMMIT();
                    CP_WAIT1();
                } else {
                    CP_WAIT0();
                }
                __syncthreads();

                uint32_t sWcur = sW_u + (uint32_t)(buf * SWBUF_HALFS) * 2;
#pragma unroll
                for (int k16 = 0; k16 < 4; k16++) {
                    int ak = kc * 64 + k16 * 16 + f_c;   // A col (halfs, global K)
                    int wk = k16 * 16 + f_c;             // W col within chunk

                    uint32_t ab[2][4], av[2][4];
#pragma unroll
                    for (int ma = 0; ma < 2; ma++) {
                        uint32_t ad = sA_u +
                            (uint32_t)((wm + ma * 16 + f_r) * AH + ak) * 2;
                        LDSM4(ab[ma][0], ab[ma][1], ab[ma][2], ab[ma][3], ad);
                        ad += (uint32_t)(128 * AH) * 2;
                        LDSM4(av[ma][0], av[ma][1], av[ma][2], av[ma][3], ad);
                    }
                    uint32_t wb[4][4], ws[4][4];
#pragma unroll
                    for (int g = 0; g < 4; g++) {
                        uint32_t off = (uint32_t)((wn + g * 16 + f_r) * WH + wk) * 2;
                        LDSM4(wb[g][0], wb[g][1], wb[g][2], wb[g][3], sWcur + off);
                        LDSM4(ws[g][0], ws[g][1], ws[g][2], ws[g][3],
                              sWcur + (uint32_t)(128 * WH) * 2 + off);
                    }
#pragma unroll
                    for (int ma = 0; ma < 2; ma++)
#pragma unroll
                        for (int g = 0; g < 4; g++)
#pragma unroll
                            for (int oc = 0; oc < 2; oc++) {
                                int na = g * 2 + oc;
                                mma_bf16(acc[ma][na], ab[ma], wb[g][oc], wb[g][oc + 2]);
                                mma_bf16(acc[ma][na], ab[ma], ws[g][oc], ws[g][oc + 2]);
                                mma_bf16(acc[ma][na], av[ma], wb[g][oc], wb[g][oc + 2]);
                            }
                }
                __syncthreads();
                buf ^= 1;
            }

            // ---- epilogue for this n-block ----
            int lr = lane >> 2, lc = lane & 3;
#pragma unroll
            for (int ma = 0; ma < 2; ma++) {
                int gr = m0 + wm + ma * 16 + lr;
#pragma unroll
                for (int na = 0; na < 8; na++) {
                    int gc = nb * 128 + wn + na * 8 + lc * 2;
                    if (gr < M)
                        *(float2*)(g_Y + (size_t)gr * WN + gc) =
                            make_float2(acc[ma][na][0], acc[ma][na][1]);
                    if (gr + 8 < M)
                        *(float2*)(g_Y + (size_t)(gr + 8) * WN + gc) =
                            make_float2(acc[ma][na][2], acc[ma][na][3]);
                }
            }
        }
    }
}

// ---------------- edge message scatter --------------------------------------
__global__ void edge_msg(const int* __restrict__ src, const int* __restrict__ dst,
                         const int* __restrict__ etype, const float* __restrict__ enorm,
                         const float* __restrict__ att) {
    int warp = (blockIdx.x * blockDim.x + threadIdx.x) >> 5;
    int lane = threadIdx.x & 31;
    if (warp >= E_EDGES) return;
    int s = src[warp];
    int d = dst[warp];
    int t = etype[warp];
    float nrm = enorm[warp];
    float4 a = *(const float4*)(att + (size_t)t * 4);
    a.x *= nrm; a.y *= nrm; a.z *= nrm; a.w *= nrm;

    const float4* y = (const float4*)(g_Y + (size_t)s * WN);
    float4 y0 = y[lane];
    float4 y1 = y[32 + lane];
    float4 y2 = y[64 + lane];
    float4 y3 = y[96 + lane];

    float4 m;
    m.x = a.x * y0.x + a.y * y1.x + a.z * y2.x + a.w * y3.x;
    m.y = a.x * y0.y + a.y * y1.y + a.z * y2.y + a.w * y3.y;
    m.z = a.x * y0.z + a.y * y1.z + a.z * y2.z + a.w * y3.z;
    m.w = a.x * y0.w + a.y * y1.w + a.z * y2.w + a.w * y3.w;

    float* o = g_AGG + (size_t)d * DIM + lane * 4;
    asm volatile("red.global.add.v4.f32 [%0], {%1, %2, %3, %4};"
                 :: "l"(o), "f"(m.x), "f"(m.y), "f"(m.z), "f"(m.w)
                 : "memory");
}

// ---------------- finalize ---------------------------------------------------
// layer-1: relu -> bf16 split for next GEMM; also re-zero AGG for layer 2.
__global__ void finalize_split_k(const float* __restrict__ bias) {
    int idx = blockIdx.x * blockDim.x + threadIdx.x;
    if (idx >= N_ENT * DIM) return;
    int n = idx >> 7, j = idx & 127;
    float v = g_AGG[idx] * g_CNT[n] + g_Y[(size_t)n * WN + NB * DIM + j] + bias[j];
    v = v > 0.0f ? v : 0.0f;
    __nv_bfloat16 hb = __float2bfloat16_rn(v);
    g_Xbh[idx] = hb;
    g_Xsh[idx] = __float2bfloat16_rn(v - __bfloat162float(hb));
    g_AGG[idx] = 0.0f;
}

__global__ void finalize_full_k(const float* __restrict__ bias) {
    int idx = blockIdx.x * blockDim.x + threadIdx.x;
    if (idx >= N_ENT * DIM) return;
    int n = idx >> 7, j = idx & 127;
    float v = g_AGG[idx] * g_CNT[n] + g_Y[(size_t)n * WN + NB * DIM + j] + bias[j];
    g_XF[idx] = v > 0.0f ? v : 0.0f;
}

// ---------------- relation GCN (tiny) ----------------------------------------
__global__ void rel_gemm1(const float* __restrict__ DAD, const float* __restrict__ RC) {
    int idx = blockIdx.x * blockDim.x + threadIdx.x;
    if (idx >= NREL * DIM) return;
    int i = idx >> 7, j = idx & 127;
    float s = 0.0f;
    for (int k = 0; k < NREL; k++) s += DAD[i * NREL + k] * RC[k * DIM + j];
    g_relT[idx] = s;
}

__global__ void rel_gemm2(const float* __restrict__ W) {
    int idx = blockIdx.x * blockDim.x + threadIdx.x;
    if (idx >= NREL * DIM) return;
    int i = idx >> 7, j = idx & 127;
    float s = 0.0f;
    for (int k = 0; k < DIM; k++) s += g_relT[i * DIM + k] * W[k * DIM + j];
    g_relC[idx] = s > 0.0f ? s : 0.0f;
}

// ---------------- gated output gather ----------------------------------------
__global__ void out_kernel(const int* __restrict__ samples,
                           const float* __restrict__ ent_emb,
                           const float* __restrict__ rel_emb,
                           const float* __restrict__ gate_e,
                           const float* __restrict__ gate_r,
                           float* __restrict__ out) {
    int idx = blockIdx.x * blockDim.x + threadIdx.x;
    if (idx >= S_SAMP * DIM) return;
    int s = idx >> 7, j = idx & 127;
    float ge = 1.0f / (1.0f + expf(-gate_e[j]));
    float gr = 1.0f / (1.0f + expf(-gate_r[j]));
    int h = samples[s * 3 + 0];
    int r = samples[s * 3 + 1];
    int t = samples[s * 3 + 2];
    out[idx] = ge * ent_emb[(size_t)h * DIM + j] + (1.0f - ge) * g_XF[(size_t)h * DIM + j];
    out[(size_t)S_SAMP * DIM + idx] =
        gr * rel_emb[(size_t)r * DIM + j] + (1.0f - gr) * g_relC[(size_t)r * DIM + j];
    out[2 * (size_t)S_SAMP * DIM + idx] =
        ge * ent_emb[(size_t)t * DIM + j] + (1.0f - ge) * g_XF[(size_t)t * DIM + j];
}

// ---------------- launch -----------------------------------------------------
extern "C" void kernel_launch(void* const* d_in, const int* in_sizes, int n_in,
                              void* d_out, int out_size) {
    const int*   entity  = (const int*)d_in[0];
    const int*   eidx    = (const int*)d_in[1];
    const int*   etype   = (const int*)d_in[2];
    const float* enorm   = (const float*)d_in[3];
    const int*   samples = (const int*)d_in[4];
    const float* DAD     = (const float*)d_in[5];
    const float* ent_emb = (const float*)d_in[6];
    const float* rel_emb = (const float*)d_in[7];
    const float* ectx    = (const float*)d_in[8];
    const float* rctx    = (const float*)d_in[9];
    const float* rgw     = (const float*)d_in[10];
    const float* gate_e  = (const float*)d_in[11];
    const float* gate_r  = (const float*)d_in[12];
    const float* basis1  = (const float*)d_in[13];
    const float* att1    = (const float*)d_in[14];
    const float* root1   = (const float*)d_in[15];
    const float* bias1   = (const float*)d_in[16];
    const float* basis2  = (const float*)d_in[17];
    const float* att2    = (const float*)d_in[18];
    const float* root2   = (const float*)d_in[19];
    const float* bias2   = (const float*)d_in[20];
    float* out = (float*)d_out;

    const int* src = eidx;
    const int* dst = eidx + E_EDGES;

    static bool attr_set = false;
    if (!attr_set) {
        cudaFuncSetAttribute(gemm_mma, cudaFuncAttributeMaxDynamicSharedMemorySize, SMEM_SZ);
        attr_set = true;
    }

    const int TB = 256;
    const long long ND = (long long)N_ENT * DIM;

    // counts (shared by both layers) + zero accumulators (one launch)
    zero_init<<<4096, TB>>>();
    count_k<<<(E_EDGES + TB - 1) / TB, TB>>>(dst);
    invcnt_k<<<(N_ENT + TB - 1) / TB, TB>>>();

    // ---- layer 1 ----
    build_w_split<<<(WN * DIM + TB - 1) / TB, TB>>>(basis1, root1);
    gather_split_x0<<<(int)((ND + TB - 1) / TB), TB>>>(entity, ectx);
    gemm_mma<<<148, TB, SMEM_SZ>>>(N_ENT);
    edge_msg<<<(E_EDGES * 32 + TB - 1) / TB, TB>>>(src, dst, etype, enorm, att1);
    finalize_split_k<<<(int)((ND + TB - 1) / TB), TB>>>(bias1);   // also zeroes AGG

    // ---- layer 2 ----
    build_w_split<<<(WN * DIM + TB - 1) / TB, TB>>>(basis2, root2);
    gemm_mma<<<148, TB, SMEM_SZ>>>(N_ENT);
    edge_msg<<<(E_EDGES * 32 + TB - 1) / TB, TB>>>(src, dst, etype, enorm, att2);
    finalize_full_k<<<(int)((ND + TB - 1) / TB), TB>>>(bias2);

    // ---- relation GCN ----
    rel_gemm1<<<(NREL * DIM + TB - 1) / TB, TB>>>(DAD, rctx);
    rel_gemm2<<<(NREL * DIM + TB - 1) / TB, TB>>>(rgw);

    // ---- gated gather ----
    out_kernel<<<(S_SAMP * DIM + TB - 1) / TB, TB>>>(samples, ent_emb, rel_emb,
                                                     gate_e, gate_r, out);
}

// round 7
// speedup vs baseline: 3.0880x; 1.1025x over previous
#include <cuda_runtime.h>
#include <cuda_bf16.h>
#include <math.h>
#include <stdint.h>

#define N_ENT   50000
#define NREL    200
#define DIM     128
#define NB      4
#define E_EDGES 200000
#define S_SAMP  20000
#define KTOT    640   /* GEMM K: 512 (Z) + 128 (X) */
#define MTILES  391   /* ceil(50000/128) */
#define CAP     128   /* slot capacity per dst (Poisson(4) -> never exceeded) */
#define CH      72    /* smem chunk row stride (halfs): 64 + pad */

// ---------------- scratch (device globals; no runtime allocation) ----------
__device__ __nv_bfloat16 g_Ab[(size_t)N_ENT * KTOT];  // A hi  = [Zmean | X]  64 MB
__device__ __nv_bfloat16 g_As[(size_t)N_ENT * KTOT];  // A lo                64 MB
__device__ __nv_bfloat16 g_Wb[DIM * KTOT];            // W^T hi [128][640]
__device__ __nv_bfloat16 g_Ws[DIM * KTOT];            // W^T lo
__device__ float g_XF[(size_t)N_ENT * DIM];           // current x (fp32)  25.6 MB
__device__ int   g_deg[N_ENT];
__device__ float g_inv[N_ENT];
__device__ int   g_slots[(size_t)N_ENT * CAP];        // 25.6 MB
__device__ float g_relT[NREL * DIM];
__device__ float g_relC[NREL * DIM];

// ---------------- PTX helpers ------------------------------------------------
__device__ __forceinline__ uint32_t smem_u32(const void* p) {
    uint32_t a;
    asm("{ .reg .u64 t; cvta.to.shared.u64 t, %1; cvt.u32.u64 %0, t; }"
        : "=r"(a) : "l"(p));
    return a;
}
__device__ __forceinline__ void cp16(uint32_t dst_s, const void* src) {
    asm volatile("cp.async.cg.shared.global [%0], [%1], 16;"
                 :: "r"(dst_s), "l"(src));
}
#define CP_COMMIT() asm volatile("cp.async.commit_group;" ::: "memory")
#define CP_WAIT1()  asm volatile("cp.async.wait_group 1;" ::: "memory")
#define CP_WAIT0()  asm volatile("cp.async.wait_group 0;" ::: "memory")

__device__ __forceinline__ void mma_bf16(float* d, const uint32_t* a,
                                         uint32_t b0, uint32_t b1) {
    asm volatile(
        "mma.sync.aligned.m16n8k16.row.col.f32.bf16.bf16.f32 "
        "{%0,%1,%2,%3}, {%4,%5,%6,%7}, {%8,%9}, {%0,%1,%2,%3};"
        : "+f"(d[0]), "+f"(d[1]), "+f"(d[2]), "+f"(d[3])
        : "r"(a[0]), "r"(a[1]), "r"(a[2]), "r"(a[3]), "r"(b0), "r"(b1));
}
#define LDSM4(r0, r1, r2, r3, addr) \
    asm volatile("ldmatrix.sync.aligned.m8n8.x4.shared.b16 {%0,%1,%2,%3}, [%4];" \
                 : "=r"(r0), "=r"(r1), "=r"(r2), "=r"(r3) : "r"(addr))

__device__ __forceinline__ uint32_t pack_bf2(float lo, float hi) {
    __nv_bfloat16 a = __float2bfloat16_rn(lo);
    __nv_bfloat16 b = __float2bfloat16_rn(hi);
    return (uint32_t)__bfloat16_as_ushort(a) |
           ((uint32_t)__bfloat16_as_ushort(b) << 16);
}
__device__ __forceinline__ void split2(float v, float& hi, float& lo) {
    __nv_bfloat16 h = __float2bfloat16_rn(v);
    hi = __bfloat162float(h);
    lo = v - hi;
}

// ---------------- setup kernels ----------------------------------------------
__global__ void zero_deg_k() {
    int i = blockIdx.x * blockDim.x + threadIdx.x;
    if (i < N_ENT) g_deg[i] = 0;
}

__global__ void fill_k(const int* __restrict__ dst) {
    int e = blockIdx.x * blockDim.x + threadIdx.x;
    if (e >= E_EDGES) return;
    int d = dst[e];
    int pos = atomicAdd(&g_deg[d], 1);
    if (pos < CAP) g_slots[(size_t)d * CAP + pos] = e;
}

__global__ void invcnt_k() {
    int i = blockIdx.x * blockDim.x + threadIdx.x;
    if (i < N_ENT) {
        int c = g_deg[i];
        g_inv[i] = 1.0f / (float)(c > 1 ? c : 1);
    }
}

// W^T[j][c]: c<512 -> basis[b=c/128][i=c%128][j] ; c>=512 -> root[c-512][j]
__global__ void build_w_split(const float* __restrict__ basis,
                              const float* __restrict__ root) {
    int idx = blockIdx.x * blockDim.x + threadIdx.x;  // DIM*KTOT
    if (idx >= DIM * KTOT) return;
    int j = idx / KTOT, c = idx % KTOT;
    float w;
    if (c < 512) w = basis[(size_t)c * DIM + j];      // (b*128+i)*128 + j
    else         w = root[(size_t)(c - 512) * DIM + j];
    float hi, lo;
    split2(w, hi, lo);
    g_Wb[idx] = __float2bfloat16_rn(hi);
    g_Ws[idx] = __float2bfloat16_rn(lo);
}

// X0 = entity_context_tab[entity] -> XF fp32 + bf16 splits into A cols 512..639
__global__ void gather_x0(const int* __restrict__ entity,
                          const float* __restrict__ ectx) {
    int idx = blockIdx.x * blockDim.x + threadIdx.x;  // N_ENT*DIM
    if (idx >= N_ENT * DIM) return;
    int n = idx >> 7, j = idx & 127;
    float x = ectx[(size_t)entity[n] * DIM + j];
    g_XF[idx] = x;
    float hi, lo;
    split2(x, hi, lo);
    g_Ab[(size_t)n * KTOT + 512 + j] = __float2bfloat16_rn(hi);
    g_As[(size_t)n * KTOT + 512 + j] = __float2bfloat16_rn(lo);
}

// ---------------- edge gather: Z[d] = inv_d * sum_e att[t_e]*norm_e (x) x[s_e]
// warp per dst; z[4 bases][4 floats] in regs; writes bf16 splits to A cols 0..511
__global__ void edge_gather(const int* __restrict__ src,
                            const int* __restrict__ etype,
                            const float* __restrict__ enorm,
                            const float* __restrict__ att) {
    int d = (blockIdx.x * blockDim.x + threadIdx.x) >> 5;
    int lane = threadIdx.x & 31;
    if (d >= N_ENT) return;
    int deg = g_deg[d];
    if (deg > CAP) deg = CAP;
    const int* slots = g_slots + (size_t)d * CAP;

    float z[16];
#pragma unroll
    for (int i = 0; i < 16; i++) z[i] = 0.0f;

    for (int i = 0; i < deg; i++) {
        int e = slots[i];
        int s = src[e];
        float nrm = enorm[e];
        float4 a = *(const float4*)(att + (size_t)etype[e] * 4);
        float4 x = ((const float4*)(g_XF + (size_t)s * DIM))[lane];
        float c;
        c = a.x * nrm; z[0] += c * x.x; z[1] += c * x.y; z[2] += c * x.z; z[3] += c * x.w;
        c = a.y * nrm; z[4] += c * x.x; z[5] += c * x.y; z[6] += c * x.z; z[7] += c * x.w;
        c = a.z * nrm; z[8] += c * x.x; z[9] += c * x.y; z[10] += c * x.z; z[11] += c * x.w;
        c = a.w * nrm; z[12] += c * x.x; z[13] += c * x.y; z[14] += c * x.z; z[15] += c * x.w;
    }

    float inv = g_inv[d];
#pragma unroll
    for (int b = 0; b < 4; b++) {
        float h0, l0, h1, l1, h2, l2, h3, l3;
        split2(z[b * 4 + 0] * inv, h0, l0);
        split2(z[b * 4 + 1] * inv, h1, l1);
        split2(z[b * 4 + 2] * inv, h2, l2);
        split2(z[b * 4 + 3] * inv, h3, l3);
        size_t off = (size_t)d * KTOT + b * 128 + lane * 4;
        *(uint2*)(g_Ab + off) = make_uint2(pack_bf2(h0, h1), pack_bf2(h2, h3));
        *(uint2*)(g_As + off) = make_uint2(pack_bf2(l0, l1), pack_bf2(l2, l3));
    }
}

// ---------------- 3xBF16 GEMM: out[M,128] = relu(A[M,640] @ W^T + bias) ------
// grid 391, 256 thr (8 warps 4m x 2n). A & W streamed in k-chunks of 64,
// double-buffered cp.async. Epilogue writes XF fp32 (+ optional bf16 splits
// into A cols 512..639 for the next layer).
#define BUF_HALFS (2 * 128 * CH)      /* per buffer: 2 splits x 128 rows x CH */
#define SMEM_SZ   (4 * BUF_HALFS * 2) /* A(2 bufs) + W(2 bufs) = 147456 B */

__device__ __forceinline__ void load_chunk(uint32_t sbase, const __nv_bfloat16* hi,
                                           const __nv_bfloat16* lo, int row0,
                                           int maxrow, size_t stride, int kc,
                                           int tid) {
    int r = tid >> 1, h = tid & 1;
    int gr = row0 + r;
    if (gr >= maxrow) gr = 0;
    const __nv_bfloat16* ph = hi + (size_t)gr * stride + kc * 64 + h * 32;
    const __nv_bfloat16* pl = lo + (size_t)gr * stride + kc * 64 + h * 32;
    uint32_t dh = sbase + (uint32_t)(r * CH + h * 32) * 2;
    uint32_t dl = dh + (uint32_t)(128 * CH) * 2;
#pragma unroll
    for (int i = 0; i < 4; i++) {
        cp16(dh + i * 16, ph + i * 8);
        cp16(dl + i * 16, pl + i * 8);
    }
}

__global__ void __launch_bounds__(256, 1)
gemm_mma(const float* __restrict__ bias, int write_split, int M) {
    extern __shared__ char smraw[];
    uint32_t sA_u = smem_u32(smraw);
    uint32_t sW_u = sA_u + 2 * BUF_HALFS * 2;

    int tid = threadIdx.x;
    int wid = tid >> 5;
    int lane = tid & 31;
    int wm = (wid & 3) * 32;
    int wn = (wid >> 2) * 64;
    int f_r = lane & 15;
    int f_c = (lane >> 4) << 3;
    int m0 = blockIdx.x * 128;

    float acc[2][8][4];
#pragma unroll
    for (int i = 0; i < 2; i++)
#pragma unroll
        for (int j = 0; j < 8; j++)
#pragma unroll
            for (int q = 0; q < 4; q++) acc[i][j][q] = 0.0f;

    load_chunk(sA_u, g_Ab, g_As, m0, M, KTOT, 0, tid);
    load_chunk(sW_u, g_Wb, g_Ws, 0, 128, KTOT, 0, tid);
    CP_COMMIT();

    int buf = 0;
    for (int kc = 0; kc < 10; kc++) {
        if (kc + 1 < 10) {
            uint32_t nb = (uint32_t)((buf ^ 1) * BUF_HALFS) * 2;
            load_chunk(sA_u + nb, g_Ab, g_As, m0, M, KTOT, kc + 1, tid);
            load_chunk(sW_u + nb, g_Wb, g_Ws, 0, 128, KTOT, kc + 1, tid);
            CP_COMMIT();
            CP_WAIT1();
        } else {
            CP_WAIT0();
        }
        __syncthreads();

        uint32_t sa = sA_u + (uint32_t)(buf * BUF_HALFS) * 2;
        uint32_t sw = sW_u + (uint32_t)(buf * BUF_HALFS) * 2;
#pragma unroll
        for (int k16 = 0; k16 < 4; k16++) {
            int ak = k16 * 16 + f_c;
            uint32_t ab[2][4], av[2][4];
#pragma unroll
            for (int ma = 0; ma < 2; ma++) {
                uint32_t ad = sa + (uint32_t)((wm + ma * 16 + f_r) * CH + ak) * 2;
                LDSM4(ab[ma][0], ab[ma][1], ab[ma][2], ab[ma][3], ad);
                ad += (uint32_t)(128 * CH) * 2;
                LDSM4(av[ma][0], av[ma][1], av[ma][2], av[ma][3], ad);
            }
            uint32_t wb[4][4], ws[4][4];
#pragma unroll
            for (int g = 0; g < 4; g++) {
                uint32_t off = (uint32_t)((wn + g * 16 + f_r) * CH + ak) * 2;
                LDSM4(wb[g][0], wb[g][1], wb[g][2], wb[g][3], sw + off);
                LDSM4(ws[g][0], ws[g][1], ws[g][2], ws[g][3],
                      sw + (uint32_t)(128 * CH) * 2 + off);
            }
#pragma unroll
            for (int ma = 0; ma < 2; ma++)
#pragma unroll
                for (int g = 0; g < 4; g++)
#pragma unroll
                    for (int oc = 0; oc < 2; oc++) {
                        int na = g * 2 + oc;
                        mma_bf16(acc[ma][na], ab[ma], wb[g][oc], wb[g][oc + 2]);
                        mma_bf16(acc[ma][na], ab[ma], ws[g][oc], ws[g][oc + 2]);
                        mma_bf16(acc[ma][na], av[ma], wb[g][oc], wb[g][oc + 2]);
                    }
        }
        __syncthreads();
        buf ^= 1;
    }

    // ---- epilogue: +bias, relu -> XF fp32 (+ bf16 splits for next layer) ----
    int lr = lane >> 2, lc = lane & 3;
#pragma unroll
    for (int ma = 0; ma < 2; ma++) {
#pragma unroll
        for (int rr = 0; rr < 2; rr++) {
            int gr = m0 + wm + ma * 16 + rr * 8 + lr;
            if (gr >= M) continue;
#pragma unroll
            for (int na = 0; na < 8; na++) {
                int gc = wn + na * 8 + lc * 2;
                float v0 = acc[ma][na][rr * 2 + 0] + bias[gc];
                float v1 = acc[ma][na][rr * 2 + 1] + bias[gc + 1];
                v0 = v0 > 0.0f ? v0 : 0.0f;
                v1 = v1 > 0.0f ? v1 : 0.0f;
                *(float2*)(g_XF + (size_t)gr * DIM + gc) = make_float2(v0, v1);
                if (write_split) {
                    float h0, l0, h1, l1;
                    split2(v0, h0, l0);
                    split2(v1, h1, l1);
                    size_t off = (size_t)gr * KTOT + 512 + gc;
                    *(uint32_t*)(g_Ab + off) = pack_bf2(h0, h1);
                    *(uint32_t*)(g_As + off) = pack_bf2(l0, l1);
                }
            }
        }
    }
}

// ---------------- relation GCN (tiny) ----------------------------------------
__global__ void rel_gemm1(const float* __restrict__ DAD, const float* __restrict__ RC) {
    int idx = blockIdx.x * blockDim.x + threadIdx.x;
    if (idx >= NREL * DIM) return;
    int i = idx >> 7, j = idx & 127;
    float s = 0.0f;
    for (int k = 0; k < NREL; k++) s += DAD[i * NREL + k] * RC[k * DIM + j];
    g_relT[idx] = s;
}

__global__ void rel_gemm2(const float* __restrict__ W) {
    int idx = blockIdx.x * blockDim.x + threadIdx.x;
    if (idx >= NREL * DIM) return;
    int i = idx >> 7, j = idx & 127;
    float s = 0.0f;
    for (int k = 0; k < DIM; k++) s += g_relT[i * DIM + k] * W[k * DIM + j];
    g_relC[idx] = s > 0.0f ? s : 0.0f;
}

// ---------------- gated output gather ----------------------------------------
__global__ void out_kernel(const int* __restrict__ samples,
                           const float* __restrict__ ent_emb,
                           const float* __restrict__ rel_emb,
                           const float* __restrict__ gate_e,
                           const float* __restrict__ gate_r,
                           float* __restrict__ out) {
    int idx = blockIdx.x * blockDim.x + threadIdx.x;
    if (idx >= S_SAMP * DIM) return;
    int s = idx >> 7, j = idx & 127;
    float ge = 1.0f / (1.0f + expf(-gate_e[j]));
    float gr = 1.0f / (1.0f + expf(-gate_r[j]));
    int h = samples[s * 3 + 0];
    int r = samples[s * 3 + 1];
    int t = samples[s * 3 + 2];
    out[idx] = ge * ent_emb[(size_t)h * DIM + j] + (1.0f - ge) * g_XF[(size_t)h * DIM + j];
    out[(size_t)S_SAMP * DIM + idx] =
        gr * rel_emb[(size_t)r * DIM + j] + (1.0f - gr) * g_relC[(size_t)r * DIM + j];
    out[2 * (size_t)S_SAMP * DIM + idx] =
        ge * ent_emb[(size_t)t * DIM + j] + (1.0f - ge) * g_XF[(size_t)t * DIM + j];
}

// ---------------- launch -----------------------------------------------------
extern "C" void kernel_launch(void* const* d_in, const int* in_sizes, int n_in,
                              void* d_out, int out_size) {
    const int*   entity  = (const int*)d_in[0];
    const int*   eidx    = (const int*)d_in[1];
    const int*   etype   = (const int*)d_in[2];
    const float* enorm   = (const float*)d_in[3];
    const int*   samples = (const int*)d_in[4];
    const float* DAD     = (const float*)d_in[5];
    const float* ent_emb = (const float*)d_in[6];
    const float* rel_emb = (const float*)d_in[7];
    const float* ectx    = (const float*)d_in[8];
    const float* rctx    = (const float*)d_in[9];
    const float* rgw     = (const float*)d_in[10];
    const float* gate_e  = (const float*)d_in[11];
    const float* gate_r  = (const float*)d_in[12];
    const float* basis1  = (const float*)d_in[13];
    const float* att1    = (const float*)d_in[14];
    const float* root1   = (const float*)d_in[15];
    const float* bias1   = (const float*)d_in[16];
    const float* basis2  = (const float*)d_in[17];
    const float* att2    = (const float*)d_in[18];
    const float* root2   = (const float*)d_in[19];
    const float* bias2   = (const float*)d_in[20];
    float* out = (float*)d_out;

    const int* src = eidx;
    const int* dst = eidx + E_EDGES;

    static bool attr_set = false;
    if (!attr_set) {
        cudaFuncSetAttribute(gemm_mma, cudaFuncAttributeMaxDynamicSharedMemorySize, SMEM_SZ);
        attr_set = true;
    }

    const int TB = 256;
    const long long ND = (long long)N_ENT * DIM;

    // ---- slot table + reciprocal counts (shared by both layers) ----
    zero_deg_k<<<(N_ENT + TB - 1) / TB, TB>>>();
    fill_k<<<(E_EDGES + TB - 1) / TB, TB>>>(dst);
    invcnt_k<<<(N_ENT + TB - 1) / TB, TB>>>();

    // ---- layer 1 ----
    build_w_split<<<(DIM * KTOT + TB - 1) / TB, TB>>>(basis1, root1);
    gather_x0<<<(int)((ND + TB - 1) / TB), TB>>>(entity, ectx);
    edge_gather<<<(N_ENT * 32 + TB - 1) / TB, TB>>>(src, etype, enorm, att1);
    gemm_mma<<<MTILES, TB, SMEM_SZ>>>(bias1, 1, N_ENT);

    // ---- layer 2 ----
    build_w_split<<<(DIM * KTOT + TB - 1) / TB, TB>>>(basis2, root2);
    edge_gather<<<(N_ENT * 32 + TB - 1) / TB, TB>>>(src, etype, enorm, att2);
    gemm_mma<<<MTILES, TB, SMEM_SZ>>>(bias2, 0, N_ENT);

    // ---- relation GCN ----
    rel_gemm1<<<(NREL * DIM + TB - 1) / TB, TB>>>(DAD, rctx);
    rel_gemm2<<<(NREL * DIM + TB - 1) / TB, TB>>>(rgw);

    // ---- gated gather ----
    out_kernel<<<(S_SAMP * DIM + TB - 1) / TB, TB>>>(samples, ent_emb, rel_emb,
                                                     gate_e, gate_r, out);
}

// round 8
// speedup vs baseline: 3.6311x; 1.1759x over previous
#include <cuda_runtime.h>
#include <cuda_bf16.h>
#include <math.h>
#include <stdint.h>

#define N_ENT   50000
#define NREL    200
#define DIM     128
#define NB      4
#define E_EDGES 200000
#define S_SAMP  20000
#define KTOT    640   /* GEMM K: 512 (Z) + 128 (X) */
#define MTILES  391   /* ceil(50000/128) */
#define CAP     128   /* slot capacity per dst */
#define CH      40    /* smem chunk row stride (halfs): 32 + pad */

// ---------------- scratch (device globals; no runtime allocation) ----------
__device__ __nv_bfloat16 g_Ab[(size_t)N_ENT * KTOT];  // A hi = [Zmean | X]
__device__ __nv_bfloat16 g_As[(size_t)N_ENT * KTOT];  // A lo
__device__ __nv_bfloat16 g_Wb[DIM * KTOT];            // W^T hi [128][640]
__device__ __nv_bfloat16 g_Ws[DIM * KTOT];            // W^T lo
__device__ float g_XF[(size_t)N_ENT * DIM];           // current x (fp32)
__device__ int   g_deg[N_ENT];
__device__ int   g_slots[(size_t)N_ENT * CAP];
__device__ float g_relT[NREL * DIM];
__device__ float g_relC[NREL * DIM];

// ---------------- PTX helpers ------------------------------------------------
__device__ __forceinline__ uint32_t smem_u32(const void* p) {
    uint32_t a;
    asm("{ .reg .u64 t; cvta.to.shared.u64 t, %1; cvt.u32.u64 %0, t; }"
        : "=r"(a) : "l"(p));
    return a;
}
__device__ __forceinline__ void cp16(uint32_t dst_s, const void* src) {
    asm volatile("cp.async.cg.shared.global [%0], [%1], 16;"
                 :: "r"(dst_s), "l"(src));
}
#define CP_COMMIT() asm volatile("cp.async.commit_group;" ::: "memory")
#define CP_WAIT1()  asm volatile("cp.async.wait_group 1;" ::: "memory")
#define CP_WAIT0()  asm volatile("cp.async.wait_group 0;" ::: "memory")

__device__ __forceinline__ void mma_bf16(float* d, const uint32_t* a,
                                         uint32_t b0, uint32_t b1) {
    asm volatile(
        "mma.sync.aligned.m16n8k16.row.col.f32.bf16.bf16.f32 "
        "{%0,%1,%2,%3}, {%4,%5,%6,%7}, {%8,%9}, {%0,%1,%2,%3};"
        : "+f"(d[0]), "+f"(d[1]), "+f"(d[2]), "+f"(d[3])
        : "r"(a[0]), "r"(a[1]), "r"(a[2]), "r"(a[3]), "r"(b0), "r"(b1));
}
#define LDSM4(r0, r1, r2, r3, addr) \
    asm volatile("ldmatrix.sync.aligned.m8n8.x4.shared.b16 {%0,%1,%2,%3}, [%4];" \
                 : "=r"(r0), "=r"(r1), "=r"(r2), "=r"(r3) : "r"(addr))

__device__ __forceinline__ uint32_t pack_bf2(float lo, float hi) {
    __nv_bfloat16 a = __float2bfloat16_rn(lo);
    __nv_bfloat16 b = __float2bfloat16_rn(hi);
    return (uint32_t)__bfloat16_as_ushort(a) |
           ((uint32_t)__bfloat16_as_ushort(b) << 16);
}
__device__ __forceinline__ void split2(float v, float& hi, float& lo) {
    __nv_bfloat16 h = __float2bfloat16_rn(v);
    hi = __bfloat162float(h);
    lo = v - hi;
}
__device__ __forceinline__ float sigmoidf(float x) {
    return 1.0f / (1.0f + expf(-x));
}

// ---------------- setup kernels ----------------------------------------------
__global__ void zero_deg_k() {
    int i = blockIdx.x * blockDim.x + threadIdx.x;
    if (i < N_ENT) g_deg[i] = 0;
}

__global__ void fill_k(const int* __restrict__ dst) {
    int e = blockIdx.x * blockDim.x + threadIdx.x;
    if (e >= E_EDGES) return;
    int d = dst[e];
    int pos = atomicAdd(&g_deg[d], 1);
    if (pos < CAP) g_slots[(size_t)d * CAP + pos] = e;
}

// W^T[j][c]: c<512 -> basis[b=c/128][i=c%128][j] ; c>=512 -> root[c-512][j]
__global__ void build_w_split(const float* __restrict__ basis,
                              const float* __restrict__ root) {
    int idx = blockIdx.x * blockDim.x + threadIdx.x;  // DIM*KTOT
    if (idx >= DIM * KTOT) return;
    int j = idx / KTOT, c = idx % KTOT;
    float w;
    if (c < 512) w = basis[(size_t)c * DIM + j];
    else         w = root[(size_t)(c - 512) * DIM + j];
    float hi, lo;
    split2(w, hi, lo);
    g_Wb[idx] = __float2bfloat16_rn(hi);
    g_Ws[idx] = __float2bfloat16_rn(lo);
}

// X0 = entity_context_tab[entity] -> XF fp32 + bf16 splits (A cols 512..639)
// float4 per thread
__global__ void gather_x0(const int* __restrict__ entity,
                          const float* __restrict__ ectx) {
    int idx = blockIdx.x * blockDim.x + threadIdx.x;  // N_ENT*32
    if (idx >= N_ENT * 32) return;
    int n = idx >> 5, q = idx & 31;
    float4 x = ((const float4*)(ectx + (size_t)entity[n] * DIM))[q];
    ((float4*)(g_XF + (size_t)n * DIM))[q] = x;
    float h0, l0, h1, l1, h2, l2, h3, l3;
    split2(x.x, h0, l0); split2(x.y, h1, l1);
    split2(x.z, h2, l2); split2(x.w, h3, l3);
    size_t off = (size_t)n * KTOT + 512 + q * 4;
    *(uint2*)(g_Ab + off) = make_uint2(pack_bf2(h0, h1), pack_bf2(h2, h3));
    *(uint2*)(g_As + off) = make_uint2(pack_bf2(l0, l1), pack_bf2(l2, l3));
}

// ---------------- edge gather: Z[d] = inv_d * sum_e (att[t_e]*norm_e) x x[s_e]
// warp per dst, 2-deep pipelined deg loop; writes bf16 splits to A cols 0..511
__global__ void edge_gather(const int* __restrict__ src,
                            const int* __restrict__ etype,
                            const float* __restrict__ enorm,
                            const float* __restrict__ att) {
    int d = (blockIdx.x * blockDim.x + threadIdx.x) >> 5;
    int lane = threadIdx.x & 31;
    if (d >= N_ENT) return;
    int degf = g_deg[d];
    int deg = degf < CAP ? degf : CAP;
    const int* slots = g_slots + (size_t)d * CAP;

    float z[16];
#pragma unroll
    for (int i = 0; i < 16; i++) z[i] = 0.0f;

    int i = 0;
    for (; i + 2 <= deg; i += 2) {
        int e0 = slots[i], e1 = slots[i + 1];
        int s0 = src[e0], s1 = src[e1];
        float n0 = enorm[e0], n1 = enorm[e1];
        float4 a0 = *(const float4*)(att + (size_t)etype[e0] * 4);
        float4 a1 = *(const float4*)(att + (size_t)etype[e1] * 4);
        float4 x0 = ((const float4*)(g_XF + (size_t)s0 * DIM))[lane];
        float4 x1 = ((const float4*)(g_XF + (size_t)s1 * DIM))[lane];
        float c;
        c = a0.x * n0; z[0]  += c * x0.x; z[1]  += c * x0.y; z[2]  += c * x0.z; z[3]  += c * x0.w;
        c = a0.y * n0; z[4]  += c * x0.x; z[5]  += c * x0.y; z[6]  += c * x0.z; z[7]  += c * x0.w;
        c = a0.z * n0; z[8]  += c * x0.x; z[9]  += c * x0.y; z[10] += c * x0.z; z[11] += c * x0.w;
        c = a0.w * n0; z[12] += c * x0.x; z[13] += c * x0.y; z[14] += c * x0.z; z[15] += c * x0.w;
        c = a1.x * n1; z[0]  += c * x1.x; z[1]  += c * x1.y; z[2]  += c * x1.z; z[3]  += c * x1.w;
        c = a1.y * n1; z[4]  += c * x1.x; z[5]  += c * x1.y; z[6]  += c * x1.z; z[7]  += c * x1.w;
        c = a1.z * n1; z[8]  += c * x1.x; z[9]  += c * x1.y; z[10] += c * x1.z; z[11] += c * x1.w;
        c = a1.w * n1; z[12] += c * x1.x; z[13] += c * x1.y; z[14] += c * x1.z; z[15] += c * x1.w;
    }
    if (i < deg) {
        int e = slots[i];
        int s = src[e];
        float nrm = enorm[e];
        float4 a = *(const float4*)(att + (size_t)etype[e] * 4);
        float4 x = ((const float4*)(g_XF + (size_t)s * DIM))[lane];
        float c;
        c = a.x * nrm; z[0]  += c * x.x; z[1]  += c * x.y; z[2]  += c * x.z; z[3]  += c * x.w;
        c = a.y * nrm; z[4]  += c * x.x; z[5]  += c * x.y; z[6]  += c * x.z; z[7]  += c * x.w;
        c = a.z * nrm; z[8]  += c * x.x; z[9]  += c * x.y; z[10] += c * x.z; z[11] += c * x.w;
        c = a.w * nrm; z[12] += c * x.x; z[13] += c * x.y; z[14] += c * x.z; z[15] += c * x.w;
    }

    float inv = 1.0f / (float)(degf > 1 ? degf : 1);
#pragma unroll
    for (int b = 0; b < 4; b++) {
        float h0, l0, h1, l1, h2, l2, h3, l3;
        split2(z[b * 4 + 0] * inv, h0, l0);
        split2(z[b * 4 + 1] * inv, h1, l1);
        split2(z[b * 4 + 2] * inv, h2, l2);
        split2(z[b * 4 + 3] * inv, h3, l3);
        size_t off = (size_t)d * KTOT + b * 128 + lane * 4;
        *(uint2*)(g_Ab + off) = make_uint2(pack_bf2(h0, h1), pack_bf2(h2, h3));
        *(uint2*)(g_As + off) = make_uint2(pack_bf2(l0, l1), pack_bf2(l2, l3));
    }
}

// ---------------- 3xBF16 GEMM: out[M,128] = relu(A[M,640] @ W^T + bias) ------
// grid 391, 256 thr (8 warps 4m x 2n), 2 CTAs/SM. 32-wide k-chunks (20 total),
// double-buffered cp.async.
#define BUF_HALFS (2 * 128 * CH)      /* 10240 halfs = 20480 B per buffer */
#define SMEM_SZ   (4 * BUF_HALFS * 2) /* A(2) + W(2) = 81920 B */

__device__ __forceinline__ void load_chunk(uint32_t sbase, const __nv_bfloat16* hi,
                                           const __nv_bfloat16* lo, int row0,
                                           int maxrow, int kc, int tid) {
    int r = tid >> 1, h = tid & 1;
    int gr = row0 + r;
    if (gr >= maxrow) gr = 0;
    const __nv_bfloat16* ph = hi + (size_t)gr * KTOT + kc * 32 + h * 16;
    const __nv_bfloat16* pl = lo + (size_t)gr * KTOT + kc * 32 + h * 16;
    uint32_t dh = sbase + (uint32_t)(r * CH + h * 16) * 2;
    uint32_t dl = dh + (uint32_t)(128 * CH) * 2;
    cp16(dh, ph);       cp16(dh + 16, ph + 8);
    cp16(dl, pl);       cp16(dl + 16, pl + 8);
}

__global__ void __launch_bounds__(256, 2)
gemm_mma(const float* __restrict__ bias, int write_split, int M) {
    extern __shared__ char smraw[];
    uint32_t sA_u = smem_u32(smraw);
    uint32_t sW_u = sA_u + 2 * BUF_HALFS * 2;

    int tid = threadIdx.x;
    int wid = tid >> 5;
    int lane = tid & 31;
    int wm = (wid & 3) * 32;
    int wn = (wid >> 2) * 64;
    int f_r = lane & 15;
    int f_c = (lane >> 4) << 3;
    int m0 = blockIdx.x * 128;

    float acc[2][8][4];
#pragma unroll
    for (int i = 0; i < 2; i++)
#pragma unroll
        for (int j = 0; j < 8; j++)
#pragma unroll
            for (int q = 0; q < 4; q++) acc[i][j][q] = 0.0f;

    load_chunk(sA_u, g_Ab, g_As, m0, M, 0, tid);
    load_chunk(sW_u, g_Wb, g_Ws, 0, 128, 0, tid);
    CP_COMMIT();

    int buf = 0;
    for (int kc = 0; kc < 20; kc++) {
        if (kc + 1 < 20) {
            uint32_t nb = (uint32_t)((buf ^ 1) * BUF_HALFS) * 2;
            load_chunk(sA_u + nb, g_Ab, g_As, m0, M, kc + 1, tid);
            load_chunk(sW_u + nb, g_Wb, g_Ws, 0, 128, kc + 1, tid);
            CP_COMMIT();
            CP_WAIT1();
        } else {
            CP_WAIT0();
        }
        __syncthreads();

        uint32_t sa = sA_u + (uint32_t)(buf * BUF_HALFS) * 2;
        uint32_t sw = sW_u + (uint32_t)(buf * BUF_HALFS) * 2;
#pragma unroll
        for (int k16 = 0; k16 < 2; k16++) {
            int ak = k16 * 16 + f_c;
            uint32_t ab[2][4], av[2][4];
#pragma unroll
            for (int ma = 0; ma < 2; ma++) {
                uint32_t ad = sa + (uint32_t)((wm + ma * 16 + f_r) * CH + ak) * 2;
                LDSM4(ab[ma][0], ab[ma][1], ab[ma][2], ab[ma][3], ad);
                ad += (uint32_t)(128 * CH) * 2;
                LDSM4(av[ma][0], av[ma][1], av[ma][2], av[ma][3], ad);
            }
            uint32_t wb[4][4], ws[4][4];
#pragma unroll
            for (int g = 0; g < 4; g++) {
                uint32_t off = (uint32_t)((wn + g * 16 + f_r) * CH + ak) * 2;
                LDSM4(wb[g][0], wb[g][1], wb[g][2], wb[g][3], sw + off);
                LDSM4(ws[g][0], ws[g][1], ws[g][2], ws[g][3],
                      sw + (uint32_t)(128 * CH) * 2 + off);
            }
#pragma unroll
            for (int ma = 0; ma < 2; ma++)
#pragma unroll
                for (int g = 0; g < 4; g++)
#pragma unroll
                    for (int oc = 0; oc < 2; oc++) {
                        int na = g * 2 + oc;
                        mma_bf16(acc[ma][na], ab[ma], wb[g][oc], wb[g][oc + 2]);
                        mma_bf16(acc[ma][na], ab[ma], ws[g][oc], ws[g][oc + 2]);
                        mma_bf16(acc[ma][na], av[ma], wb[g][oc], wb[g][oc + 2]);
                    }
        }
        __syncthreads();
        buf ^= 1;
    }

    // ---- epilogue: +bias, relu -> XF fp32 (+ bf16 splits for next layer) ----
    int lr = lane >> 2, lc = lane & 3;
#pragma unroll
    for (int ma = 0; ma < 2; ma++) {
#pragma unroll
        for (int rr = 0; rr < 2; rr++) {
            int gr = m0 + wm + ma * 16 + rr * 8 + lr;
            if (gr >= M) continue;
#pragma unroll
            for (int na = 0; na < 8; na++) {
                int gc = wn + na * 8 + lc * 2;
                float v0 = acc[ma][na][rr * 2 + 0] + bias[gc];
                float v1 = acc[ma][na][rr * 2 + 1] + bias[gc + 1];
                v0 = v0 > 0.0f ? v0 : 0.0f;
                v1 = v1 > 0.0f ? v1 : 0.0f;
                *(float2*)(g_XF + (size_t)gr * DIM + gc) = make_float2(v0, v1);
                if (write_split) {
                    float h0, l0, h1, l1;
                    split2(v0, h0, l0);
                    split2(v1, h1, l1);
                    size_t off = (size_t)gr * KTOT + 512 + gc;
                    *(uint32_t*)(g_Ab + off) = pack_bf2(h0, h1);
                    *(uint32_t*)(g_As + off) = pack_bf2(l0, l1);
                }
            }
        }
    }
}

// ---------------- relation GCN (tiny) ----------------------------------------
__global__ void rel_gemm1(const float* __restrict__ DAD, const float* __restrict__ RC) {
    int idx = blockIdx.x * blockDim.x + threadIdx.x;
    if (idx >= NREL * DIM) return;
    int i = idx >> 7, j = idx & 127;
    float s = 0.0f;
    for (int k = 0; k < NREL; k++) s += DAD[i * NREL + k] * RC[k * DIM + j];
    g_relT[idx] = s;
}

__global__ void rel_gemm2(const float* __restrict__ W) {
    int idx = blockIdx.x * blockDim.x + threadIdx.x;
    if (idx >= NREL * DIM) return;
    int i = idx >> 7, j = idx & 127;
    float s = 0.0f;
    for (int k = 0; k < DIM; k++) s += g_relT[i * DIM + k] * W[k * DIM + j];
    g_relC[idx] = s > 0.0f ? s : 0.0f;
}

// ---------------- gated output gather (float4/thread) ------------------------
__global__ void out_kernel(const int* __restrict__ samples,
                           const float* __restrict__ ent_emb,
                           const float* __restrict__ rel_emb,
                           const float* __restrict__ gate_e,
                           const float* __restrict__ gate_r,
                           float* __restrict__ out) {
    int idx = blockIdx.x * blockDim.x + threadIdx.x;  // S_SAMP*32
    if (idx >= S_SAMP * 32) return;
    int s = idx >> 5, q = idx & 31;
    float4 gev = ((const float4*)gate_e)[q];
    float4 grv = ((const float4*)gate_r)[q];
    float4 ge = make_float4(sigmoidf(gev.x), sigmoidf(gev.y), sigmoidf(gev.z), sigmoidf(gev.w));
    float4 gr = make_float4(sigmoidf(grv.x), sigmoidf(grv.y), sigmoidf(grv.z), sigmoidf(grv.w));
    int h = samples[s * 3 + 0];
    int r = samples[s * 3 + 1];
    int t = samples[s * 3 + 2];

    float4 a, b, o;
    a = ((const float4*)(ent_emb + (size_t)h * DIM))[q];
    b = ((const float4*)(g_XF + (size_t)h * DIM))[q];
    o.x = ge.x * a.x + (1.0f - ge.x) * b.x;
    o.y = ge.y * a.y + (1.0f - ge.y) * b.y;
    o.z = ge.z * a.z + (1.0f - ge.z) * b.z;
    o.w = ge.w * a.w + (1.0f - ge.w) * b.w;
    ((float4*)out)[idx] = o;

    a = ((const float4*)(rel_emb + (size_t)r * DIM))[q];
    b = ((const float4*)(g_relC + (size_t)r * DIM))[q];
    o.x = gr.x * a.x + (1.0f - gr.x) * b.x;
    o.y = gr.y * a.y + (1.0f - gr.y) * b.y;
    o.z = gr.z * a.z + (1.0f - gr.z) * b.z;
    o.w = gr.w * a.w + (1.0f - gr.w) * b.w;
    ((float4*)out)[S_SAMP * 32 + idx] = o;

    a = ((const float4*)(ent_emb + (size_t)t * DIM))[q];
    b = ((const float4*)(g_XF + (size_t)t * DIM))[q];
    o.x = ge.x * a.x + (1.0f - ge.x) * b.x;
    o.y = ge.y * a.y + (1.0f - ge.y) * b.y;
    o.z = ge.z * a.z + (1.0f - ge.z) * b.z;
    o.w = ge.w * a.w + (1.0f - ge.w) * b.w;
    ((float4*)out)[2 * S_SAMP * 32 + idx] = o;
}

// ---------------- launch -----------------------------------------------------
extern "C" void kernel_launch(void* const* d_in, const int* in_sizes, int n_in,
                              void* d_out, int out_size) {
    const int*   entity  = (const int*)d_in[0];
    const int*   eidx    = (const int*)d_in[1];
    const int*   etype   = (const int*)d_in[2];
    const float* enorm   = (const float*)d_in[3];
    const int*   samples = (const int*)d_in[4];
    const float* DAD     = (const float*)d_in[5];
    const float* ent_emb = (const float*)d_in[6];
    const float* rel_emb = (const float*)d_in[7];
    const float* ectx    = (const float*)d_in[8];
    const float* rctx    = (const float*)d_in[9];
    const float* rgw     = (const float*)d_in[10];
    const float* gate_e  = (const float*)d_in[11];
    const float* gate_r  = (const float*)d_in[12];
    const float* basis1  = (const float*)d_in[13];
    const float* att1    = (const float*)d_in[14];
    const float* root1   = (const float*)d_in[15];
    const float* bias1   = (const float*)d_in[16];
    const float* basis2  = (const float*)d_in[17];
    const float* att2    = (const float*)d_in[18];
    const float* root2   = (const float*)d_in[19];
    const float* bias2   = (const float*)d_in[20];
    float* out = (float*)d_out;

    const int* src = eidx;
    const int* dst = eidx + E_EDGES;

    static bool attr_set = false;
    if (!attr_set) {
        cudaFuncSetAttribute(gemm_mma, cudaFuncAttributeMaxDynamicSharedMemorySize, SMEM_SZ);
        attr_set = true;
    }

    const int TB = 256;

    // ---- slot table + degrees (shared by both layers) ----
    zero_deg_k<<<(N_ENT + TB - 1) / TB, TB>>>();
    fill_k<<<(E_EDGES + TB - 1) / TB, TB>>>(dst);

    // ---- layer 1 ----
    build_w_split<<<(DIM * KTOT + TB - 1) / TB, TB>>>(basis1, root1);
    gather_x0<<<(N_ENT * 32 + TB - 1) / TB, TB>>>(entity, ectx);
    edge_gather<<<(N_ENT * 32 + TB - 1) / TB, TB>>>(src, etype, enorm, att1);
    gemm_mma<<<MTILES, TB, SMEM_SZ>>>(bias1, 1, N_ENT);

    // ---- layer 2 ----
    build_w_split<<<(DIM * KTOT + TB - 1) / TB, TB>>>(basis2, root2);
    edge_gather<<<(N_ENT * 32 + TB - 1) / TB, TB>>>(src, etype, enorm, att2);
    gemm_mma<<<MTILES, TB, SMEM_SZ>>>(bias2, 0, N_ENT);

    // ---- relation GCN ----
    rel_gemm1<<<(NREL * DIM + TB - 1) / TB, TB>>>(DAD, rctx);
    rel_gemm2<<<(NREL * DIM + TB - 1) / TB, TB>>>(rgw);

    // ---- gated gather ----
    out_kernel<<<(S_SAMP * 32 + TB - 1) / TB, TB>>>(samples, ent_emb, rel_emb,
                                                    gate_e, gate_r, out);
}

// round 9
// speedup vs baseline: 3.6531x; 1.0061x over previous
#include <cuda_runtime.h>
#include <cuda_bf16.h>
#include <math.h>
#include <stdint.h>

#define N_ENT   50000
#define NREL    200
#define DIM     128
#define NB      4
#define E_EDGES 200000
#define S_SAMP  20000
#define KTOT    640   /* GEMM K: 512 (Z) + 128 (X) */
#define MTILES  391   /* ceil(50000/128) */
#define CAP     128   /* slot capacity per dst */
#define CH      40    /* smem chunk row stride (halfs): 32 + pad */

// ---------------- scratch (device globals; no runtime allocation) ----------
__device__ __nv_bfloat16 g_Ab[(size_t)N_ENT * KTOT];  // A hi = [Zmean | X]
__device__ __nv_bfloat16 g_As[(size_t)N_ENT * KTOT];  // A lo
__device__ __nv_bfloat16 g_Wb[2][DIM * KTOT];         // W^T hi, per layer
__device__ __nv_bfloat16 g_Ws[2][DIM * KTOT];         // W^T lo, per layer
__device__ float g_XF[(size_t)N_ENT * DIM];           // current x (fp32)
__device__ int   g_deg[N_ENT];
__device__ int   g_slots[(size_t)N_ENT * CAP];
__device__ float g_relT[NREL * DIM];
__device__ float g_relC[NREL * DIM];

// ---------------- PTX helpers ------------------------------------------------
__device__ __forceinline__ uint32_t smem_u32(const void* p) {
    uint32_t a;
    asm("{ .reg .u64 t; cvta.to.shared.u64 t, %1; cvt.u32.u64 %0, t; }"
        : "=r"(a) : "l"(p));
    return a;
}
__device__ __forceinline__ void cp16(uint32_t dst_s, const void* src) {
    asm volatile("cp.async.cg.shared.global [%0], [%1], 16;"
                 :: "r"(dst_s), "l"(src));
}
#define CP_COMMIT() asm volatile("cp.async.commit_group;" ::: "memory")
#define CP_WAIT1()  asm volatile("cp.async.wait_group 1;" ::: "memory")
#define CP_WAIT0()  asm volatile("cp.async.wait_group 0;" ::: "memory")

__device__ __forceinline__ void mma_bf16(float* d, const uint32_t* a,
                                         uint32_t b0, uint32_t b1) {
    asm volatile(
        "mma.sync.aligned.m16n8k16.row.col.f32.bf16.bf16.f32 "
        "{%0,%1,%2,%3}, {%4,%5,%6,%7}, {%8,%9}, {%0,%1,%2,%3};"
        : "+f"(d[0]), "+f"(d[1]), "+f"(d[2]), "+f"(d[3])
        : "r"(a[0]), "r"(a[1]), "r"(a[2]), "r"(a[3]), "r"(b0), "r"(b1));
}
#define LDSM4(r0, r1, r2, r3, addr) \
    asm volatile("ldmatrix.sync.aligned.m8n8.x4.shared.b16 {%0,%1,%2,%3}, [%4];" \
                 : "=r"(r0), "=r"(r1), "=r"(r2), "=r"(r3) : "r"(addr))

__device__ __forceinline__ uint32_t pack_bf2(float lo, float hi) {
    __nv_bfloat16 a = __float2bfloat16_rn(lo);
    __nv_bfloat16 b = __float2bfloat16_rn(hi);
    return (uint32_t)__bfloat16_as_ushort(a) |
           ((uint32_t)__bfloat16_as_ushort(b) << 16);
}
__device__ __forceinline__ void split2(float v, float& hi, float& lo) {
    __nv_bfloat16 h = __float2bfloat16_rn(v);
    hi = __bfloat162float(h);
    lo = v - hi;
}
__device__ __forceinline__ float sigmoidf(float x) {
    return 1.0f / (1.0f + expf(-x));
}

// ---------------- setup kernels ----------------------------------------------
__global__ void zero_deg_k() {
    int i = blockIdx.x * blockDim.x + threadIdx.x;
    if (i < N_ENT) g_deg[i] = 0;
}

__global__ void fill_k(const int* __restrict__ dst) {
    int e = blockIdx.x * blockDim.x + threadIdx.x;
    if (e >= E_EDGES) return;
    int d = dst[e];
    int pos = atomicAdd(&g_deg[d], 1);
    if (pos < CAP) g_slots[(size_t)d * CAP + pos] = e;
}

// W^T[j][c]: c<512 -> basis[b=c/128][i=c%128][j] ; c>=512 -> root[c-512][j]
__global__ void build_w_split(const float* __restrict__ basis,
                              const float* __restrict__ root, int layer) {
    int idx = blockIdx.x * blockDim.x + threadIdx.x;  // DIM*KTOT
    if (idx >= DIM * KTOT) return;
    int j = idx / KTOT, c = idx % KTOT;
    float w;
    if (c < 512) w = basis[(size_t)c * DIM + j];
    else         w = root[(size_t)(c - 512) * DIM + j];
    float hi, lo;
    split2(w, hi, lo);
    g_Wb[layer][idx] = __float2bfloat16_rn(hi);
    g_Ws[layer][idx] = __float2bfloat16_rn(lo);
}

// X0 = entity_context_tab[entity] -> XF fp32 + bf16 splits (A cols 512..639)
__global__ void gather_x0(const int* __restrict__ entity,
                          const float* __restrict__ ectx) {
    int idx = blockIdx.x * blockDim.x + threadIdx.x;  // N_ENT*32
    if (idx >= N_ENT * 32) return;
    int n = idx >> 5, q = idx & 31;
    float4 x = ((const float4*)(ectx + (size_t)entity[n] * DIM))[q];
    ((float4*)(g_XF + (size_t)n * DIM))[q] = x;
    float h0, l0, h1, l1, h2, l2, h3, l3;
    split2(x.x, h0, l0); split2(x.y, h1, l1);
    split2(x.z, h2, l2); split2(x.w, h3, l3);
    size_t off = (size_t)n * KTOT + 512 + q * 4;
    *(uint2*)(g_Ab + off) = make_uint2(pack_bf2(h0, h1), pack_bf2(h2, h3));
    *(uint2*)(g_As + off) = make_uint2(pack_bf2(l0, l1), pack_bf2(l2, l3));
}

// ---------------- edge gather -------------------------------------------------
__device__ __forceinline__ void accum16(float* z, float4 a, float nrm, float4 x) {
    float c;
    c = a.x * nrm; z[0]  += c * x.x; z[1]  += c * x.y; z[2]  += c * x.z; z[3]  += c * x.w;
    c = a.y * nrm; z[4]  += c * x.x; z[5]  += c * x.y; z[6]  += c * x.z; z[7]  += c * x.w;
    c = a.z * nrm; z[8]  += c * x.x; z[9]  += c * x.y; z[10] += c * x.z; z[11] += c * x.w;
    c = a.w * nrm; z[12] += c * x.x; z[13] += c * x.y; z[14] += c * x.z; z[15] += c * x.w;
}

// warp per dst; 4-deep pipelined deg loop; writes bf16 splits to A cols 0..511
__global__ void edge_gather(const int* __restrict__ src,
                            const int* __restrict__ etype,
                            const float* __restrict__ enorm,
                            const float* __restrict__ att) {
    int d = (blockIdx.x * blockDim.x + threadIdx.x) >> 5;
    int lane = threadIdx.x & 31;
    if (d >= N_ENT) return;
    int degf = g_deg[d];
    int deg = degf < CAP ? degf : CAP;
    const int* slots = g_slots + (size_t)d * CAP;

    float z[16];
#pragma unroll
    for (int i = 0; i < 16; i++) z[i] = 0.0f;

    int i = 0;
    for (; i + 4 <= deg; i += 4) {
        int4 sl = *(const int4*)(slots + i);      // 16B-aligned (i % 4 == 0)
        int s0 = src[sl.x], s1 = src[sl.y], s2 = src[sl.z], s3 = src[sl.w];
        float n0 = enorm[sl.x], n1 = enorm[sl.y], n2 = enorm[sl.z], n3 = enorm[sl.w];
        float4 a0 = *(const float4*)(att + (size_t)etype[sl.x] * 4);
        float4 a1 = *(const float4*)(att + (size_t)etype[sl.y] * 4);
        float4 a2 = *(const float4*)(att + (size_t)etype[sl.z] * 4);
        float4 a3 = *(const float4*)(att + (size_t)etype[sl.w] * 4);
        float4 x0 = ((const float4*)(g_XF + (size_t)s0 * DIM))[lane];
        float4 x1 = ((const float4*)(g_XF + (size_t)s1 * DIM))[lane];
        float4 x2 = ((const float4*)(g_XF + (size_t)s2 * DIM))[lane];
        float4 x3 = ((const float4*)(g_XF + (size_t)s3 * DIM))[lane];
        accum16(z, a0, n0, x0);
        accum16(z, a1, n1, x1);
        accum16(z, a2, n2, x2);
        accum16(z, a3, n3, x3);
    }
    if (i + 2 <= deg) {
        int e0 = slots[i], e1 = slots[i + 1];
        int s0 = src[e0], s1 = src[e1];
        float n0 = enorm[e0], n1 = enorm[e1];
        float4 a0 = *(const float4*)(att + (size_t)etype[e0] * 4);
        float4 a1 = *(const float4*)(att + (size_t)etype[e1] * 4);
        float4 x0 = ((const float4*)(g_XF + (size_t)s0 * DIM))[lane];
        float4 x1 = ((const float4*)(g_XF + (size_t)s1 * DIM))[lane];
        accum16(z, a0, n0, x0);
        accum16(z, a1, n1, x1);
        i += 2;
    }
    if (i < deg) {
        int e = slots[i];
        int s = src[e];
        float nrm = enorm[e];
        float4 a = *(const float4*)(att + (size_t)etype[e] * 4);
        float4 x = ((const float4*)(g_XF + (size_t)s * DIM))[lane];
        accum16(z, a, nrm, x);
    }

    float inv = 1.0f / (float)(degf > 1 ? degf : 1);
#pragma unroll
    for (int b = 0; b < 4; b++) {
        float h0, l0, h1, l1, h2, l2, h3, l3;
        split2(z[b * 4 + 0] * inv, h0, l0);
        split2(z[b * 4 + 1] * inv, h1, l1);
        split2(z[b * 4 + 2] * inv, h2, l2);
        split2(z[b * 4 + 3] * inv, h3, l3);
        size_t off = (size_t)d * KTOT + b * 128 + lane * 4;
        *(uint2*)(g_Ab + off) = make_uint2(pack_bf2(h0, h1), pack_bf2(h2, h3));
        *(uint2*)(g_As + off) = make_uint2(pack_bf2(l0, l1), pack_bf2(l2, l3));
    }
}

// ---------------- 3xBF16 GEMM: out[M,128] = relu(A[M,640] @ W^T + bias) ------
#define BUF_HALFS (2 * 128 * CH)      /* 10240 halfs = 20480 B per buffer */
#define SMEM_SZ   (4 * BUF_HALFS * 2) /* A(2) + W(2) = 81920 B */

__device__ __forceinline__ void load_chunk(uint32_t sbase, const __nv_bfloat16* hi,
                                           const __nv_bfloat16* lo, int row0,
                                           int maxrow, int kc, int tid) {
    int r = tid >> 1, h = tid & 1;
    int gr = row0 + r;
    if (gr >= maxrow) gr = 0;
    const __nv_bfloat16* ph = hi + (size_t)gr * KTOT + kc * 32 + h * 16;
    const __nv_bfloat16* pl = lo + (size_t)gr * KTOT + kc * 32 + h * 16;
    uint32_t dh = sbase + (uint32_t)(r * CH + h * 16) * 2;
    uint32_t dl = dh + (uint32_t)(128 * CH) * 2;
    cp16(dh, ph);       cp16(dh + 16, ph + 8);
    cp16(dl, pl);       cp16(dl + 16, pl + 8);
}

__global__ void __launch_bounds__(256, 2)
gemm_mma(const float* __restrict__ bias, int write_split, int layer, int M) {
    extern __shared__ char smraw[];
    uint32_t sA_u = smem_u32(smraw);
    uint32_t sW_u = sA_u + 2 * BUF_HALFS * 2;
    const __nv_bfloat16* Wb = g_Wb[layer];
    const __nv_bfloat16* Ws = g_Ws[layer];

    int tid = threadIdx.x;
    int wid = tid >> 5;
    int lane = tid & 31;
    int wm = (wid & 3) * 32;
    int wn = (wid >> 2) * 64;
    int f_r = lane & 15;
    int f_c = (lane >> 4) << 3;
    int m0 = blockIdx.x * 128;

    float acc[2][8][4];
#pragma unroll
    for (int i = 0; i < 2; i++)
#pragma unroll
        for (int j = 0; j < 8; j++)
#pragma unroll
            for (int q = 0; q < 4; q++) acc[i][j][q] = 0.0f;

    load_chunk(sA_u, g_Ab, g_As, m0, M, 0, tid);
    load_chunk(sW_u, Wb, Ws, 0, 128, 0, tid);
    CP_COMMIT();

    int buf = 0;
    for (int kc = 0; kc < 20; kc++) {
        if (kc + 1 < 20) {
            uint32_t nb = (uint32_t)((buf ^ 1) * BUF_HALFS) * 2;
            load_chunk(sA_u + nb, g_Ab, g_As, m0, M, kc + 1, tid);
            load_chunk(sW_u + nb, Wb, Ws, 0, 128, kc + 1, tid);
            CP_COMMIT();
            CP_WAIT1();
        } else {
            CP_WAIT0();
        }
        __syncthreads();

        uint32_t sa = sA_u + (uint32_t)(buf * BUF_HALFS) * 2;
        uint32_t sw = sW_u + (uint32_t)(buf * BUF_HALFS) * 2;
#pragma unroll
        for (int k16 = 0; k16 < 2; k16++) {
            int ak = k16 * 16 + f_c;
            uint32_t ab[2][4], av[2][4];
#pragma unroll
            for (int ma = 0; ma < 2; ma++) {
                uint32_t ad = sa + (uint32_t)((wm + ma * 16 + f_r) * CH + ak) * 2;
                LDSM4(ab[ma][0], ab[ma][1], ab[ma][2], ab[ma][3], ad);
                ad += (uint32_t)(128 * CH) * 2;
                LDSM4(av[ma][0], av[ma][1], av[ma][2], av[ma][3], ad);
            }
            uint32_t wb[4][4], ws[4][4];
#pragma unroll
            for (int g = 0; g < 4; g++) {
                uint32_t off = (uint32_t)((wn + g * 16 + f_r) * CH + ak) * 2;
                LDSM4(wb[g][0], wb[g][1], wb[g][2], wb[g][3], sw + off);
                LDSM4(ws[g][0], ws[g][1], ws[g][2], ws[g][3],
                      sw + (uint32_t)(128 * CH) * 2 + off);
            }
#pragma unroll
            for (int ma = 0; ma < 2; ma++)
#pragma unroll
                for (int g = 0; g < 4; g++)
#pragma unroll
                    for (int oc = 0; oc < 2; oc++) {
                        int na = g * 2 + oc;
                        mma_bf16(acc[ma][na], ab[ma], wb[g][oc], wb[g][oc + 2]);
                        mma_bf16(acc[ma][na], ab[ma], ws[g][oc], ws[g][oc + 2]);
                        mma_bf16(acc[ma][na], av[ma], wb[g][oc], wb[g][oc + 2]);
                    }
        }
        __syncthreads();
        buf ^= 1;
    }

    // ---- epilogue ----
    int lr = lane >> 2, lc = lane & 3;
#pragma unroll
    for (int ma = 0; ma < 2; ma++) {
#pragma unroll
        for (int rr = 0; rr < 2; rr++) {
            int gr = m0 + wm + ma * 16 + rr * 8 + lr;
            if (gr >= M) continue;
#pragma unroll
            for (int na = 0; na < 8; na++) {
                int gc = wn + na * 8 + lc * 2;
                float v0 = acc[ma][na][rr * 2 + 0] + bias[gc];
                float v1 = acc[ma][na][rr * 2 + 1] + bias[gc + 1];
                v0 = v0 > 0.0f ? v0 : 0.0f;
                v1 = v1 > 0.0f ? v1 : 0.0f;
                *(float2*)(g_XF + (size_t)gr * DIM + gc) = make_float2(v0, v1);
                if (write_split) {
                    float h0, l0, h1, l1;
                    split2(v0, h0, l0);
                    split2(v1, h1, l1);
                    size_t off = (size_t)gr * KTOT + 512 + gc;
                    *(uint32_t*)(g_Ab + off) = pack_bf2(h0, h1);
                    *(uint32_t*)(g_As + off) = pack_bf2(l0, l1);
                }
            }
        }
    }
}

// ---------------- relation GCN (tiny) ----------------------------------------
__global__ void rel_gemm1(const float* __restrict__ DAD, const float* __restrict__ RC) {
    int idx = blockIdx.x * blockDim.x + threadIdx.x;
    if (idx >= NREL * DIM) return;
    int i = idx >> 7, j = idx & 127;
    float s = 0.0f;
    for (int k = 0; k < NREL; k++) s += DAD[i * NREL + k] * RC[k * DIM + j];
    g_relT[idx] = s;
}

__global__ void rel_gemm2(const float* __restrict__ W) {
    int idx = blockIdx.x * blockDim.x + threadIdx.x;
    if (idx >= NREL * DIM) return;
    int i = idx >> 7, j = idx & 127;
    float s = 0.0f;
    for (int k = 0; k < DIM; k++) s += g_relT[i * DIM + k] * W[k * DIM + j];
    g_relC[idx] = s > 0.0f ? s : 0.0f;
}

// ---------------- gated output gather (float4/thread) ------------------------
__global__ void out_kernel(const int* __restrict__ samples,
                           const float* __restrict__ ent_emb,
                           const float* __restrict__ rel_emb,
                           const float* __restrict__ gate_e,
                           const float* __restrict__ gate_r,
                           float* __restrict__ out) {
    int idx = blockIdx.x * blockDim.x + threadIdx.x;  // S_SAMP*32
    if (idx >= S_SAMP * 32) return;
    int s = idx >> 5, q = idx & 31;
    float4 gev = ((const float4*)gate_e)[q];
    float4 grv = ((const float4*)gate_r)[q];
    float4 ge = make_float4(sigmoidf(gev.x), sigmoidf(gev.y), sigmoidf(gev.z), sigmoidf(gev.w));
    float4 gr = make_float4(sigmoidf(grv.x), sigmoidf(grv.y), sigmoidf(grv.z), sigmoidf(grv.w));
    int h = samples[s * 3 + 0];
    int r = samples[s * 3 + 1];
    int t = samples[s * 3 + 2];

    float4 a, b, o;
    a = ((const float4*)(ent_emb + (size_t)h * DIM))[q];
    b = ((const float4*)(g_XF + (size_t)h * DIM))[q];
    o.x = ge.x * a.x + (1.0f - ge.x) * b.x;
    o.y = ge.y * a.y + (1.0f - ge.y) * b.y;
    o.z = ge.z * a.z + (1.0f - ge.z) * b.z;
    o.w = ge.w * a.w + (1.0f - ge.w) * b.w;
    ((float4*)out)[idx] = o;

    a = ((const float4*)(rel_emb + (size_t)r * DIM))[q];
    b = ((const float4*)(g_relC + (size_t)r * DIM))[q];
    o.x = gr.x * a.x + (1.0f - gr.x) * b.x;
    o.y = gr.y * a.y + (1.0f - gr.y) * b.y;
    o.z = gr.z * a.z + (1.0f - gr.z) * b.z;
    o.w = gr.w * a.w + (1.0f - gr.w) * b.w;
    ((float4*)out)[S_SAMP * 32 + idx] = o;

    a = ((const float4*)(ent_emb + (size_t)t * DIM))[q];
    b = ((const float4*)(g_XF + (size_t)t * DIM))[q];
    o.x = ge.x * a.x + (1.0f - ge.x) * b.x;
    o.y = ge.y * a.y + (1.0f - ge.y) * b.y;
    o.z = ge.z * a.z + (1.0f - ge.z) * b.z;
    o.w = ge.w * a.w + (1.0f - ge.w) * b.w;
    ((float4*)out)[2 * S_SAMP * 32 + idx] = o;
}

// ---------------- launch -----------------------------------------------------
extern "C" void kernel_launch(void* const* d_in, const int* in_sizes, int n_in,
                              void* d_out, int out_size) {
    const int*   entity  = (const int*)d_in[0];
    const int*   eidx    = (const int*)d_in[1];
    const int*   etype   = (const int*)d_in[2];
    const float* enorm   = (const float*)d_in[3];
    const int*   samples = (const int*)d_in[4];
    const float* DAD     = (const float*)d_in[5];
    const float* ent_emb = (const float*)d_in[6];
    const float* rel_emb = (const float*)d_in[7];
    const float* ectx    = (const float*)d_in[8];
    const float* rctx    = (const float*)d_in[9];
    const float* rgw     = (const float*)d_in[10];
    const float* gate_e  = (const float*)d_in[11];
    const float* gate_r  = (const float*)d_in[12];
    const float* basis1  = (const float*)d_in[13];
    const float* att1    = (const float*)d_in[14];
    const float* root1   = (const float*)d_in[15];
    const float* bias1   = (const float*)d_in[16];
    const float* basis2  = (const float*)d_in[17];
    const float* att2    = (const float*)d_in[18];
    const float* root2   = (const float*)d_in[19];
    const float* bias2   = (const float*)d_in[20];
    float* out = (float*)d_out;

    const int* src = eidx;
    const int* dst = eidx + E_EDGES;

    static bool init_done = false;
    static cudaStream_t s1;
    static cudaEvent_t evRoot, evX0, evW1, evW2, evRel;
    if (!init_done) {
        cudaFuncSetAttribute(gemm_mma, cudaFuncAttributeMaxDynamicSharedMemorySize, SMEM_SZ);
        cudaStreamCreateWithFlags(&s1, cudaStreamNonBlocking);
        cudaEventCreateWithFlags(&evRoot, cudaEventDisableTiming);
        cudaEventCreateWithFlags(&evX0,   cudaEventDisableTiming);
        cudaEventCreateWithFlags(&evW1,   cudaEventDisableTiming);
        cudaEventCreateWithFlags(&evW2,   cudaEventDisableTiming);
        cudaEventCreateWithFlags(&evRel,  cudaEventDisableTiming);
        init_done = true;
    }

    const int TB = 256;

    // fork side stream off the (capture) default stream
    cudaEventRecord(evRoot, 0);
    cudaStreamWaitEvent(s1, evRoot, 0);

    // ---- main stream: slot table + degrees ----
    zero_deg_k<<<(N_ENT + TB - 1) / TB, TB>>>();
    fill_k<<<(E_EDGES + TB - 1) / TB, TB>>>(dst);

    // ---- side stream: gather_x0, W splits, relation GCN ----
    gather_x0<<<(N_ENT * 32 + TB - 1) / TB, TB, 0, s1>>>(entity, ectx);
    cudaEventRecord(evX0, s1);
    build_w_split<<<(DIM * KTOT + TB - 1) / TB, TB, 0, s1>>>(basis1, root1, 0);
    cudaEventRecord(evW1, s1);
    build_w_split<<<(DIM * KTOT + TB - 1) / TB, TB, 0, s1>>>(basis2, root2, 1);
    cudaEventRecord(evW2, s1);
    rel_gemm1<<<(NREL * DIM + TB - 1) / TB, TB, 0, s1>>>(DAD, rctx);
    rel_gemm2<<<(NREL * DIM + TB - 1) / TB, TB, 0, s1>>>(rgw);
    cudaEventRecord(evRel, s1);

    // ---- layer 1 (main stream) ----
    cudaStreamWaitEvent(0, evX0, 0);
    edge_gather<<<(N_ENT * 32 + TB - 1) / TB, TB>>>(src, etype, enorm, att1);
    cudaStreamWaitEvent(0, evW1, 0);
    gemm_mma<<<MTILES, TB, SMEM_SZ>>>(bias1, 1, 0, N_ENT);

    // ---- layer 2 ----
    edge_gather<<<(N_ENT * 32 + TB - 1) / TB, TB>>>(src, etype, enorm, att2);
    cudaStreamWaitEvent(0, evW2, 0);
    gemm_mma<<<MTILES, TB, SMEM_SZ>>>(bias2, 0, 1, N_ENT);

    // ---- gated gather ----
    cudaStreamWaitEvent(0, evRel, 0);
    out_kernel<<<(S_SAMP * 32 + TB - 1) / TB, TB>>>(samples, ent_emb, rel_emb,
                                                    gate_e, gate_r, out);
}